// round 5
// baseline (speedup 1.0000x reference)
#include <cuda_runtime.h>
#include <cuda_bf16.h>
#include <cstdint>

#define SLEN    2048
#define DHEAD   64
#define BHN     64
#define TQ      64
#define TK      64
#define NTHREADS 128
#define NKT     (SLEN / TK)                      // 32
#define OUT_ELEMS ((size_t)BHN * SLEN * DHEAD)   // 8,388,608
#define TILE_B  8192                             // one 64x64 bf16 tile, bytes

// XOR swizzle for 128-byte rows: bits[6:4] ^= bits[9:7]
#define SWZ(x) ((x) ^ ((((x) >> 3) & 0x70)))

// ---------------- pre-converted scratch (16 MB each, 100 MB total) ----------------
// K/V: [bh][kt][8192-byte swizzled tile]; Q: row-major bf16 [bh][r][d]
__device__ __align__(128) uint8_t g_KH[BHN * NKT * TILE_B];
__device__ __align__(128) uint8_t g_KL[BHN * NKT * TILE_B];
__device__ __align__(128) uint8_t g_VH[BHN * NKT * TILE_B];   // V transposed: [d][k]
__device__ __align__(128) uint8_t g_VL[BHN * NKT * TILE_B];
__device__ __align__(128) __nv_bfloat16 g_QH[(size_t)BHN * SLEN * DHEAD];
__device__ __align__(128) __nv_bfloat16 g_QL[(size_t)BHN * SLEN * DHEAD];

static __device__ __forceinline__ uint32_t pack2(float hi, float lo) {
    uint32_t r;
    asm("cvt.rn.bf16x2.f32 %0, %1, %2;" : "=r"(r) : "f"(hi), "f"(lo));
    return r;
}
static __device__ __forceinline__ float bfr(float x) {
    return __bfloat162float(__float2bfloat16(x));
}
static __device__ __forceinline__ void split4(float4 v, uint2& hi, uint2& lo) {
    float h0 = bfr(v.x), h1 = bfr(v.y), h2 = bfr(v.z), h3 = bfr(v.w);
    hi.x = pack2(h1, h0);
    hi.y = pack2(h3, h2);
    lo.x = pack2(v.y - h1, v.x - h0);
    lo.y = pack2(v.w - h3, v.z - h2);
}
static __device__ __forceinline__ uint32_t smem_u32(const void* p) {
    uint32_t a;
    asm("{ .reg .u64 t; cvta.to.shared.u64 t, %1; cvt.u32.u64 %0, t; }" : "=r"(a) : "l"(p));
    return a;
}
static __device__ __forceinline__ void cp16(uint32_t sm, const void* g) {
    asm volatile("cp.async.cg.shared.global [%0], [%1], 16;" :: "r"(sm), "l"(g));
}
static __device__ __forceinline__ void mma_bf16(float* c, const uint32_t* a,
                                                uint32_t b0, uint32_t b1) {
    asm volatile("mma.sync.aligned.m16n8k16.row.col.f32.bf16.bf16.f32 "
                 "{%0,%1,%2,%3}, {%4,%5,%6,%7}, {%8,%9}, {%0,%1,%2,%3};"
                 : "+f"(c[0]), "+f"(c[1]), "+f"(c[2]), "+f"(c[3])
                 : "r"(a[0]), "r"(a[1]), "r"(a[2]), "r"(a[3]), "r"(b0), "r"(b1));
}

// ================= prep: fp32 -> bf16 hi/lo, tiled + swizzled (+V transpose) =================
__global__ void __launch_bounds__(NTHREADS)
prep_kernel(const float* __restrict__ Q, const float* __restrict__ K,
            const float* __restrict__ V)
{
    const int kt = blockIdx.x, bh = blockIdx.y, mode = blockIdx.z;
    const int tid = threadIdx.x;
    const size_t base_f = (size_t)bh * SLEN * DHEAD + (size_t)kt * TK * DHEAD;
    const size_t tile_o = ((size_t)bh * NKT + kt) * TILE_B;

    if (mode == 0) {            // K tile: [c][d], swizzled
        const float* src = K + base_f;
#pragma unroll
        for (int it = 0; it < 8; ++it) {
            const int idx = tid + it * NTHREADS;   // 1024 float4 groups
            const int c = idx >> 4, dg = idx & 15;
            float4 v = *(const float4*)(src + c * DHEAD + dg * 4);
            uint2 hi, lo; split4(v, hi, lo);
            const uint32_t bo = SWZ((uint32_t)(c * 128 + dg * 8));
            *(uint2*)(g_KH + tile_o + bo) = hi;
            *(uint2*)(g_KL + tile_o + bo) = lo;
        }
    } else if (mode == 1) {     // V tile transposed: [d][k], swizzled
        const float* src = V + base_f;
#pragma unroll
        for (int it = 0; it < 8; ++it) {
            const int idx = tid + it * NTHREADS;
            const int d = idx & 63, kg = idx >> 6;
            const float* vp = src + (size_t)kg * 4 * DHEAD + d;
            float4 v = make_float4(vp[0], vp[DHEAD], vp[2 * DHEAD], vp[3 * DHEAD]);
            uint2 hi, lo; split4(v, hi, lo);
            const uint32_t bo = SWZ((uint32_t)(d * 128 + kg * 8));
            *(uint2*)(g_VH + tile_o + bo) = hi;
            *(uint2*)(g_VL + tile_o + bo) = lo;
        }
    } else {                    // Q rows: plain row-major bf16 hi/lo
        const float* src = Q + base_f;
        __nv_bfloat16* qh = g_QH + base_f;
        __nv_bfloat16* ql = g_QL + base_f;
#pragma unroll
        for (int it = 0; it < 8; ++it) {
            const int idx = tid + it * NTHREADS;
            float4 v = *(const float4*)(src + idx * 4);
            uint2 hi, lo; split4(v, hi, lo);
            *(uint2*)(qh + idx * 4) = hi;
            *(uint2*)(ql + idx * 4) = lo;
        }
    }
}

// ================= main attention kernel =================
// dynamic smem layout (bytes)
#define OFF_KH 0
#define OFF_KL 16384
#define OFF_VH 32768
#define OFF_VL 49152
#define OFF_RS 65536
#define SMEM_BYTES (65536 + 256)

__global__ void __launch_bounds__(NTHREADS)
sdpa_mma_kernel(const int* __restrict__ Mg_all,
                float* __restrict__ Og_all,
                float* __restrict__ Ag_all)
{
    extern __shared__ uint8_t smem[];
    const uint32_t smb = smem_u32(smem);
    float* rowsum = (float*)(smem + OFF_RS);

    const int tid = threadIdx.x;
    const int w   = tid >> 5;
    const int l   = tid & 31;
    const int bh  = blockIdx.y;
    const int q0  = blockIdx.x * TQ;

    const int* Mg = Mg_all + (size_t)bh * SLEN * SLEN;
    float*     Og = Og_all + (size_t)bh * SLEN * DHEAD;
    float*     Ag = Ag_all + (size_t)bh * SLEN * SLEN;

    const uint8_t* gKH = g_KH + (size_t)bh * NKT * TILE_B;
    const uint8_t* gKL = g_KL + (size_t)bh * NKT * TILE_B;
    const uint8_t* gVH = g_VH + (size_t)bh * NKT * TILE_B;
    const uint8_t* gVL = g_VL + (size_t)bh * NKT * TILE_B;

    // ---- issue one tile's 4 buffers via cp.async (4 x 16B per thread per buffer) ----
    auto issue_tile = [&](int kt, int s) {
        if (kt < NKT) {
            const uint32_t so = (uint32_t)(s * TILE_B + tid * 16);
            const size_t   go = (size_t)kt * TILE_B + tid * 16;
#pragma unroll
            for (int j = 0; j < 4; ++j) {
                cp16(smb + OFF_KH + so + j * 2048, gKH + go + j * 2048);
                cp16(smb + OFF_KL + so + j * 2048, gKL + go + j * 2048);
                cp16(smb + OFF_VH + so + j * 2048, gVH + go + j * 2048);
                cp16(smb + OFF_VL + so + j * 2048, gVL + go + j * 2048);
            }
        }
        asm volatile("cp.async.commit_group;" ::: "memory");
    };

    // prologue: prefetch tiles 0 and 1
    issue_tile(0, 0);
    issue_tile(1, 1);

    // ---- Q fragments from pre-converted global (held in regs all 32 tiles) ----
    const int r0 = q0 + w * 16 + (l >> 2);
    uint32_t qh[4][4], ql[4][4];
    {
        const __nv_bfloat16* q0p = g_QH + (size_t)bh * SLEN * DHEAD + (size_t)r0 * DHEAD;
        const __nv_bfloat16* q1p = g_QL + (size_t)bh * SLEN * DHEAD + (size_t)r0 * DHEAD;
#pragma unroll
        for (int ks = 0; ks < 4; ++ks) {
            const int d0 = ks * 16 + (l & 3) * 2;
            qh[ks][0] = *(const uint32_t*)(q0p + d0);
            qh[ks][1] = *(const uint32_t*)(q0p + 8 * DHEAD + d0);
            qh[ks][2] = *(const uint32_t*)(q0p + d0 + 8);
            qh[ks][3] = *(const uint32_t*)(q0p + 8 * DHEAD + d0 + 8);
            ql[ks][0] = *(const uint32_t*)(q1p + d0);
            ql[ks][1] = *(const uint32_t*)(q1p + 8 * DHEAD + d0);
            ql[ks][2] = *(const uint32_t*)(q1p + d0 + 8);
            ql[ks][3] = *(const uint32_t*)(q1p + 8 * DHEAD + d0 + 8);
        }
    }

    // per-lane swizzled B-fragment offsets
    uint32_t koff[4];
#pragma unroll
    for (int ks = 0; ks < 4; ++ks)
        koff[ks] = (uint32_t)(((l >> 2) * 128 + ks * 32 + (l & 3) * 4) ^ ((l >> 2) << 4));

    float oacc[8][4];
#pragma unroll
    for (int nb = 0; nb < 8; ++nb) { oacc[nb][0]=0.f; oacc[nb][1]=0.f; oacc[nb][2]=0.f; oacc[nb][3]=0.f; }
    float rs0 = 0.f, rs1 = 0.f;

    const int* mb0base = Mg + (size_t)r0 * SLEN + (l & 3) * 2;
    float*     ab0base = Ag + (size_t)r0 * SLEN + (l & 3) * 2;

    for (int kt = 0; kt < NKT; ++kt) {
        const int kc0 = kt * TK;
        const uint32_t sb = (uint32_t)((kt & 1) * TILE_B);

        asm volatile("cp.async.wait_group 1;" ::: "memory");
        __syncthreads();   // tile kt resident; all warps past previous tile

        // ---- mask prefetch (hidden under S MMAs) ----
        const int* mr0 = mb0base + kc0;
        const int* mr8 = mr0 + 8 * SLEN;
        int2 m0[8], m1[8];
#pragma unroll
        for (int nb = 0; nb < 8; ++nb) {
            m0[nb] = *(const int2*)(mr0 + nb * 8);
            m1[nb] = *(const int2*)(mr8 + nb * 8);
        }

        // ---- S = Qh Kh + Qh Kl + Ql Kh ----
        const uint8_t* KH = smem + OFF_KH + sb;
        const uint8_t* KL = smem + OFF_KL + sb;
        float sacc[8][4];
#pragma unroll
        for (int nb = 0; nb < 8; ++nb) { sacc[nb][0]=0.f; sacc[nb][1]=0.f; sacc[nb][2]=0.f; sacc[nb][3]=0.f; }
#pragma unroll
        for (int ks = 0; ks < 4; ++ks) {
#pragma unroll
            for (int nb = 0; nb < 8; ++nb) {
                const uint32_t o = koff[ks] + nb * 1024;
                const uint32_t kh0 = *(const uint32_t*)(KH + o);
                const uint32_t kh1 = *(const uint32_t*)(KH + (o ^ 16));
                const uint32_t kl0 = *(const uint32_t*)(KL + o);
                const uint32_t kl1 = *(const uint32_t*)(KL + (o ^ 16));
                mma_bf16(sacc[nb], qh[ks], kh0, kh1);
                mma_bf16(sacc[nb], qh[ks], kl0, kl1);
                mma_bf16(sacc[nb], ql[ks], kh0, kh1);
            }
        }

        // ---- mask + exp, attn write (unnormalized), P -> A fragments ----
        float* ar0 = ab0base + kc0;
        float* ar8 = ar0 + 8 * SLEN;
        uint32_t phi[4][4], plo[4][4];
#pragma unroll
        for (int nb = 0; nb < 8; ++nb) {
            float p0 = m0[nb].x ? __expf(sacc[nb][0] * 0.125f) : 0.f;
            float p1 = m0[nb].y ? __expf(sacc[nb][1] * 0.125f) : 0.f;
            float p2 = m1[nb].x ? __expf(sacc[nb][2] * 0.125f) : 0.f;
            float p3 = m1[nb].y ? __expf(sacc[nb][3] * 0.125f) : 0.f;
            rs0 += p0 + p1;
            rs1 += p2 + p3;
            *(float2*)(ar0 + nb * 8) = make_float2(p0, p1);
            *(float2*)(ar8 + nb * 8) = make_float2(p2, p3);
            const float h0 = bfr(p0), h1 = bfr(p1), h2 = bfr(p2), h3 = bfr(p3);
            const int j = nb >> 1, hf = (nb & 1) * 2;
            phi[j][hf + 0] = pack2(h1, h0);
            phi[j][hf + 1] = pack2(h3, h2);
            plo[j][hf + 0] = pack2(p1 - h1, p0 - h0);
            plo[j][hf + 1] = pack2(p3 - h3, p2 - h2);
        }

        // ---- O += Ph Vh + Ph Vl + Pl Vh ----
        const uint8_t* VH = smem + OFF_VH + sb;
        const uint8_t* VL = smem + OFF_VL + sb;
#pragma unroll
        for (int j = 0; j < 4; ++j) {
#pragma unroll
            for (int nb = 0; nb < 8; ++nb) {
                const uint32_t o = koff[j] + nb * 1024;
                const uint32_t vh0 = *(const uint32_t*)(VH + o);
                const uint32_t vh1 = *(const uint32_t*)(VH + (o ^ 16));
                const uint32_t vl0 = *(const uint32_t*)(VL + o);
                const uint32_t vl1 = *(const uint32_t*)(VL + (o ^ 16));
                mma_bf16(oacc[nb], phi[j], vh0, vh1);
                mma_bf16(oacc[nb], phi[j], vl0, vl1);
                mma_bf16(oacc[nb], plo[j], vh0, vh1);
            }
        }

        __syncthreads();              // everyone done reading buffer kt&1
        issue_tile(kt + 2, kt & 1);   // overwrite it with tile kt+2
    }

    // ---- row sums: reduce 4 lanes per row, invert ----
    rs0 += __shfl_xor_sync(0xffffffffu, rs0, 1);
    rs0 += __shfl_xor_sync(0xffffffffu, rs0, 2);
    rs1 += __shfl_xor_sync(0xffffffffu, rs1, 1);
    rs1 += __shfl_xor_sync(0xffffffffu, rs1, 2);
    if ((l & 3) == 0) {
        rowsum[w * 16 + (l >> 2)]     = rs0;
        rowsum[w * 16 + 8 + (l >> 2)] = rs1;
    }
    __syncthreads();
    if (tid < TQ) rowsum[tid] = 1.0f / rowsum[tid];
    __syncthreads();

    // ---- write normalized O ----
    {
        const float inv0 = rowsum[w * 16 + (l >> 2)];
        const float inv1 = rowsum[w * 16 + 8 + (l >> 2)];
        float* or0 = Og + (size_t)r0 * DHEAD + (l & 3) * 2;
        float* or8 = or0 + 8 * DHEAD;
#pragma unroll
        for (int nb = 0; nb < 8; ++nb) {
            *(float2*)(or0 + nb * 8) = make_float2(oacc[nb][0] * inv0, oacc[nb][1] * inv0);
            *(float2*)(or8 + nb * 8) = make_float2(oacc[nb][2] * inv1, oacc[nb][3] * inv1);
        }
    }

    // ---- normalize this block's attention rows ----
    for (int idx = tid; idx < TQ * (SLEN / 4); idx += NTHREADS) {
        const int rr = idx >> 9;
        const int cg = idx & 511;
        const float inv = rowsum[rr];
        float4* p = (float4*)(Ag + (size_t)(q0 + rr) * SLEN) + cg;
        float4 v = *p;
        v.x *= inv; v.y *= inv; v.z *= inv; v.w *= inv;
        *p = v;
    }
}

extern "C" void kernel_launch(void* const* d_in, const int* in_sizes, int n_in,
                              void* d_out, int out_size)
{
    const float* Q    = (const float*)d_in[0];
    const float* K    = (const float*)d_in[1];
    const float* V    = (const float*)d_in[2];
    const int*   mask = (const int*)d_in[3];
    (void)in_sizes; (void)n_in; (void)out_size;

    float* out  = (float*)d_out;
    float* attn = out + OUT_ELEMS;

    static int configured = 0;
    if (!configured) {
        cudaFuncSetAttribute(sdpa_mma_kernel,
                             cudaFuncAttributeMaxDynamicSharedMemorySize, SMEM_BYTES);
        configured = 1;
    }

    dim3 pgrid(NKT, BHN, 3);                 // (32, 64, 3)
    prep_kernel<<<pgrid, NTHREADS>>>(Q, K, V);

    dim3 grid(SLEN / TQ, BHN);               // (32, 64)
    sdpa_mma_kernel<<<grid, NTHREADS, SMEM_BYTES>>>(mask, out, attn);
}

// round 6
// speedup vs baseline: 1.0009x; 1.0009x over previous
#include <cuda_runtime.h>
#include <cuda_bf16.h>
#include <cstdint>

#define SLEN    2048
#define DHEAD   64
#define BHN     64
#define TQ      64
#define TK      64
#define NTHREADS 128
#define NKT     (SLEN / TK)
#define OUT_ELEMS ((size_t)BHN * SLEN * DHEAD)   // 8,388,608

// XOR swizzle for 128-byte rows (8B granular): bits[6:4] ^= bits[9:7]
#define SWZ(x) ((x) ^ ((((x) >> 3) & 0x70)))

// 64x64 int/float tile, 256B rows, 8-word groups XOR-swizzled by row
#define MIDX(r, c) (((r) << 8) + ((((((c) >> 3) ^ ((r) & 7)) << 3) + ((c) & 7)) << 2))

// ---- dynamic smem layout (bytes) ----
#define OFF_KH  0
#define OFF_KL  8192
#define OFF_VH  16384
#define OFF_VL  24576
#define OFF_MSK 32768                 // 16 KB mask tile (swizzled)
#define OFF_AST 49152                 // 16 KB attn stage (swizzled)
#define OFF_RS  65536
#define SMEM_BYTES (65536 + 256)

static __device__ __forceinline__ uint32_t pack2(float hi, float lo) {
    uint32_t r;
    asm("cvt.rn.bf16x2.f32 %0, %1, %2;" : "=r"(r) : "f"(hi), "f"(lo));
    return r;
}
static __device__ __forceinline__ float bfr(float x) {
    return __bfloat162float(__float2bfloat16(x));
}
static __device__ __forceinline__ void split4(float4 v, uint2& hi, uint2& lo) {
    float h0 = bfr(v.x), h1 = bfr(v.y), h2 = bfr(v.z), h3 = bfr(v.w);
    hi.x = pack2(h1, h0);
    hi.y = pack2(h3, h2);
    lo.x = pack2(v.y - h1, v.x - h0);
    lo.y = pack2(v.w - h3, v.z - h2);
}
static __device__ __forceinline__ uint32_t smem_u32(const void* p) {
    uint32_t a;
    asm("{ .reg .u64 t; cvta.to.shared.u64 t, %1; cvt.u32.u64 %0, t; }" : "=r"(a) : "l"(p));
    return a;
}
static __device__ __forceinline__ void cp16(uint32_t sm, const void* g) {
    asm volatile("cp.async.cg.shared.global [%0], [%1], 16;" :: "r"(sm), "l"(g));
}
static __device__ __forceinline__ void mma_bf16(float* c, const uint32_t* a,
                                                uint32_t b0, uint32_t b1) {
    asm volatile("mma.sync.aligned.m16n8k16.row.col.f32.bf16.bf16.f32 "
                 "{%0,%1,%2,%3}, {%4,%5,%6,%7}, {%8,%9}, {%0,%1,%2,%3};"
                 : "+f"(c[0]), "+f"(c[1]), "+f"(c[2]), "+f"(c[3])
                 : "r"(a[0]), "r"(a[1]), "r"(a[2]), "r"(a[3]), "r"(b0), "r"(b1));
}

__global__ void __launch_bounds__(NTHREADS)
sdpa_mma_kernel(const float* __restrict__ Qg_all,
                const float* __restrict__ Kg_all,
                const float* __restrict__ Vg_all,
                const int*   __restrict__ Mg_all,
                float* __restrict__ Og_all,
                float* __restrict__ Ag_all)
{
    extern __shared__ uint8_t smem[];
    const uint32_t smb = smem_u32(smem);
    uint8_t* KH = smem + OFF_KH;
    uint8_t* KL = smem + OFF_KL;
    uint8_t* VH = smem + OFF_VH;
    uint8_t* VL = smem + OFF_VL;
    uint8_t* MS = smem + OFF_MSK;
    uint8_t* AS = smem + OFF_AST;
    float* rowsum = (float*)(smem + OFF_RS);

    const int tid = threadIdx.x;
    const int w   = tid >> 5;
    const int l   = tid & 31;
    const int bh  = blockIdx.y;
    const int q0  = blockIdx.x * TQ;

    const float* Qg = Qg_all + (size_t)bh * SLEN * DHEAD;
    const float* Kg = Kg_all + (size_t)bh * SLEN * DHEAD;
    const float* Vg = Vg_all + (size_t)bh * SLEN * DHEAD;
    const int*   Mg = Mg_all + (size_t)bh * SLEN * SLEN;
    float*       Og = Og_all + (size_t)bh * SLEN * DHEAD;
    float*       Ag = Ag_all + (size_t)bh * SLEN * SLEN;

    // ---- Q fragments straight from global (kept in regs all 32 tiles) ----
    const int r0 = q0 + w * 16 + (l >> 2);
    uint32_t qh[4][4], ql[4][4];
    {
        const float* Qr0 = Qg + (size_t)r0 * DHEAD;
        const float* Qr8 = Qr0 + 8 * DHEAD;
#pragma unroll
        for (int ks = 0; ks < 4; ++ks) {
            const int d0 = ks * 16 + (l & 3) * 2;
            float2 q00 = *(const float2*)(Qr0 + d0);
            float2 q01 = *(const float2*)(Qr0 + d0 + 8);
            float2 q10 = *(const float2*)(Qr8 + d0);
            float2 q11 = *(const float2*)(Qr8 + d0 + 8);
            float h00x = bfr(q00.x), h00y = bfr(q00.y);
            float h10x = bfr(q10.x), h10y = bfr(q10.y);
            float h01x = bfr(q01.x), h01y = bfr(q01.y);
            float h11x = bfr(q11.x), h11y = bfr(q11.y);
            qh[ks][0] = pack2(h00y, h00x);  ql[ks][0] = pack2(q00.y - h00y, q00.x - h00x);
            qh[ks][1] = pack2(h10y, h10x);  ql[ks][1] = pack2(q10.y - h10y, q10.x - h10x);
            qh[ks][2] = pack2(h01y, h01x);  ql[ks][2] = pack2(q01.y - h01y, q01.x - h01x);
            qh[ks][3] = pack2(h11y, h11x);  ql[ks][3] = pack2(q11.y - h11y, q11.x - h11x);
        }
    }

    // per-lane swizzled bf16-tile B-fragment offsets
    uint32_t koff[4];
#pragma unroll
    for (int ks = 0; ks < 4; ++ks)
        koff[ks] = (uint32_t)(((l >> 2) * 128 + ks * 32 + (l & 3) * 4) ^ ((l >> 2) << 4));

    // fragment-layout offsets into the swizzled 64x64 int/float tiles
    const int rl0 = w * 16 + (l >> 2);          // local row, first half
    uint32_t foff0[8], foff8[8];
#pragma unroll
    for (int nb = 0; nb < 8; ++nb) {
        foff0[nb] = (uint32_t)MIDX(rl0,     nb * 8 + (l & 3) * 2);
        foff8[nb] = (uint32_t)MIDX(rl0 + 8, nb * 8 + (l & 3) * 2);
    }

    float oacc[8][4];
#pragma unroll
    for (int nb = 0; nb < 8; ++nb) { oacc[nb][0]=0.f; oacc[nb][1]=0.f; oacc[nb][2]=0.f; oacc[nb][3]=0.f; }
    float rs0 = 0.f, rs1 = 0.f;

    for (int kt = 0; kt < NKT; ++kt) {
        const int kc0 = kt * TK;

        __syncthreads();   // K/V/MSK buffers free; AST readers done

        // ---- mask tile -> swizzled smem via cp.async (coalesced, no regs) ----
#pragma unroll
        for (int it = 0; it < 8; ++it) {
            const int idx = tid + it * NTHREADS;         // 1024 int4 groups
            const int r = idx >> 4, cg = idx & 15;
            cp16(smb + OFF_MSK + MIDX(r, cg * 4),
                 Mg + (size_t)(q0 + r) * SLEN + kc0 + cg * 4);
        }
        asm volatile("cp.async.commit_group;" ::: "memory");

        // ---- K tile [c][d] -> bf16 hi/lo smem ----
#pragma unroll
        for (int it = 0; it < 8; ++it) {
            const int idx = tid + it * NTHREADS;
            const int c = idx >> 4, dg = idx & 15;
            float4 v = *(const float4*)(Kg + (size_t)(kc0 + c) * DHEAD + dg * 4);
            uint2 hi, lo; split4(v, hi, lo);
            const uint32_t bo = SWZ((uint32_t)(c * 128 + dg * 8));
            *(uint2*)(KH + bo) = hi;
            *(uint2*)(KL + bo) = lo;
        }
        // ---- V tile transposed [d][k] -> bf16 hi/lo smem ----
#pragma unroll
        for (int it = 0; it < 8; ++it) {
            const int idx = tid + it * NTHREADS;
            const int d = idx & 63, kg = idx >> 6;
            const float* vp = Vg + (size_t)(kc0 + kg * 4) * DHEAD + d;
            float4 v = make_float4(vp[0], vp[DHEAD], vp[2 * DHEAD], vp[3 * DHEAD]);
            uint2 hi, lo; split4(v, hi, lo);
            const uint32_t bo = SWZ((uint32_t)(d * 128 + kg * 8));
            *(uint2*)(VH + bo) = hi;
            *(uint2*)(VL + bo) = lo;
        }
        asm volatile("cp.async.wait_group 0;" ::: "memory");
        __syncthreads();

        // ---- S = Qh Kh + Qh Kl + Ql Kh ----
        float sacc[8][4];
#pragma unroll
        for (int nb = 0; nb < 8; ++nb) { sacc[nb][0]=0.f; sacc[nb][1]=0.f; sacc[nb][2]=0.f; sacc[nb][3]=0.f; }
#pragma unroll
        for (int ks = 0; ks < 4; ++ks) {
#pragma unroll
            for (int nb = 0; nb < 8; ++nb) {
                const uint32_t o = koff[ks] + nb * 1024;
                const uint32_t kh0 = *(const uint32_t*)(KH + o);
                const uint32_t kh1 = *(const uint32_t*)(KH + (o ^ 16));
                const uint32_t kl0 = *(const uint32_t*)(KL + o);
                const uint32_t kl1 = *(const uint32_t*)(KL + (o ^ 16));
                mma_bf16(sacc[nb], qh[ks], kh0, kh1);
                mma_bf16(sacc[nb], qh[ks], kl0, kl1);
                mma_bf16(sacc[nb], ql[ks], kh0, kh1);
            }
        }

        // ---- mask (smem) + exp, stage attn frags to smem, build P frags ----
        int2 m0[8], m1[8];
#pragma unroll
        for (int nb = 0; nb < 8; ++nb) {
            m0[nb] = *(const int2*)(MS + foff0[nb]);
            m1[nb] = *(const int2*)(MS + foff8[nb]);
        }
        uint32_t phi[4][4], plo[4][4];
#pragma unroll
        for (int nb = 0; nb < 8; ++nb) {
            float p0 = m0[nb].x ? __expf(sacc[nb][0] * 0.125f) : 0.f;
            float p1 = m0[nb].y ? __expf(sacc[nb][1] * 0.125f) : 0.f;
            float p2 = m1[nb].x ? __expf(sacc[nb][2] * 0.125f) : 0.f;
            float p3 = m1[nb].y ? __expf(sacc[nb][3] * 0.125f) : 0.f;
            rs0 += p0 + p1;
            rs1 += p2 + p3;
            *(float2*)(AS + foff0[nb]) = make_float2(p0, p1);
            *(float2*)(AS + foff8[nb]) = make_float2(p2, p3);
            const float h0 = bfr(p0), h1 = bfr(p1), h2 = bfr(p2), h3 = bfr(p3);
            const int j = nb >> 1, hf = (nb & 1) * 2;
            phi[j][hf + 0] = pack2(h1, h0);
            phi[j][hf + 1] = pack2(h3, h2);
            plo[j][hf + 0] = pack2(p1 - h1, p0 - h0);
            plo[j][hf + 1] = pack2(p3 - h3, p2 - h2);
        }
        __syncthreads();   // attn stage complete

        // ---- coalesced attn store (drains under the PV MMAs) ----
#pragma unroll
        for (int it = 0; it < 8; ++it) {
            const int idx = tid + it * NTHREADS;
            const int r = idx >> 4, cg = idx & 15;
            float4 v = *(const float4*)(AS + MIDX(r, cg * 4));
            *(float4*)(Ag + (size_t)(q0 + r) * SLEN + kc0 + cg * 4) = v;  // unnormalized
        }

        // ---- O += Ph Vh + Ph Vl + Pl Vh ----
#pragma unroll
        for (int j = 0; j < 4; ++j) {
#pragma unroll
            for (int nb = 0; nb < 8; ++nb) {
                const uint32_t o = koff[j] + nb * 1024;
                const uint32_t vh0 = *(const uint32_t*)(VH + o);
                const uint32_t vh1 = *(const uint32_t*)(VH + (o ^ 16));
                const uint32_t vl0 = *(const uint32_t*)(VL + o);
                const uint32_t vl1 = *(const uint32_t*)(VL + (o ^ 16));
                mma_bf16(oacc[nb], phi[j], vh0, vh1);
                mma_bf16(oacc[nb], phi[j], vl0, vl1);
                mma_bf16(oacc[nb], plo[j], vh0, vh1);
            }
        }
    }

    // ---- row sums: reduce 4 lanes per row, invert ----
    rs0 += __shfl_xor_sync(0xffffffffu, rs0, 1);
    rs0 += __shfl_xor_sync(0xffffffffu, rs0, 2);
    rs1 += __shfl_xor_sync(0xffffffffu, rs1, 1);
    rs1 += __shfl_xor_sync(0xffffffffu, rs1, 2);
    if ((l & 3) == 0) {
        rowsum[w * 16 + (l >> 2)]     = rs0;
        rowsum[w * 16 + 8 + (l >> 2)] = rs1;
    }
    __syncthreads();
    if (tid < TQ) rowsum[tid] = 1.0f / rowsum[tid];
    __syncthreads();

    // ---- write normalized O ----
    {
        const float inv0 = rowsum[w * 16 + (l >> 2)];
        const float inv1 = rowsum[w * 16 + 8 + (l >> 2)];
        float* or0 = Og + (size_t)r0 * DHEAD + (l & 3) * 2;
        float* or8 = or0 + 8 * DHEAD;
#pragma unroll
        for (int nb = 0; nb < 8; ++nb) {
            *(float2*)(or0 + nb * 8) = make_float2(oacc[nb][0] * inv0, oacc[nb][1] * inv0);
            *(float2*)(or8 + nb * 8) = make_float2(oacc[nb][2] * inv1, oacc[nb][3] * inv1);
        }
    }

    // ---- normalize this block's attention rows (coalesced stream) ----
    for (int idx = tid; idx < TQ * (SLEN / 4); idx += NTHREADS) {
        const int rr = idx >> 9;
        const int cg = idx & 511;
        const float inv = rowsum[rr];
        float4* p = (float4*)(Ag + (size_t)(q0 + rr) * SLEN) + cg;
        float4 v = *p;
        v.x *= inv; v.y *= inv; v.z *= inv; v.w *= inv;
        *p = v;
    }
}

extern "C" void kernel_launch(void* const* d_in, const int* in_sizes, int n_in,
                              void* d_out, int out_size)
{
    const float* Q    = (const float*)d_in[0];
    const float* K    = (const float*)d_in[1];
    const float* V    = (const float*)d_in[2];
    const int*   mask = (const int*)d_in[3];
    (void)in_sizes; (void)n_in; (void)out_size;

    float* out  = (float*)d_out;
    float* attn = out + OUT_ELEMS;

    static int configured = 0;
    if (!configured) {
        cudaFuncSetAttribute(sdpa_mma_kernel,
                             cudaFuncAttributeMaxDynamicSharedMemorySize, SMEM_BYTES);
        configured = 1;
    }

    dim3 grid(SLEN / TQ, BHN);   // (32, 64)
    sdpa_mma_kernel<<<grid, NTHREADS, SMEM_BYTES>>>(Q, K, V, mask, out, attn);
}

// round 7
// speedup vs baseline: 1.2099x; 1.2088x over previous
#include <cuda_runtime.h>
#include <cuda_bf16.h>
#include <cstdint>

#define SLEN    2048
#define DHEAD   64
#define BHN     64
#define TQ      64
#define TK      64
#define NTHREADS 128
#define NKT     (SLEN / TK)
#define OUT_ELEMS ((size_t)BHN * SLEN * DHEAD)   // 8,388,608

// XOR swizzle for 128-byte rows (8B granular): bits[6:4] ^= bits[9:7]
#define SWZ(x) ((x) ^ ((((x) >> 3) & 0x70)))

// ---- dynamic smem layout (bytes) ----
#define OFF_KH 0
#define OFF_KL 8192
#define OFF_VH 16384
#define OFF_VL 24576
#define OFF_BM 32768                    // 64 rows x 68 words bitmask = 17408 B
#define OFF_RS 50176                    // 64 floats
#define SMEM_BYTES 50432
#define BM_STRIDE 68                    // words per bitmask row (pad kills bank conflicts)

static __device__ __forceinline__ uint32_t pack2(float hi, float lo) {
    uint32_t r;
    asm("cvt.rn.bf16x2.f32 %0, %1, %2;" : "=r"(r) : "f"(hi), "f"(lo));
    return r;
}
static __device__ __forceinline__ float bfr(float x) {
    return __bfloat162float(__float2bfloat16(x));
}
static __device__ __forceinline__ void split4(float4 v, uint2& hi, uint2& lo) {
    float h0 = bfr(v.x), h1 = bfr(v.y), h2 = bfr(v.z), h3 = bfr(v.w);
    hi.x = pack2(h1, h0);
    hi.y = pack2(h3, h2);
    lo.x = pack2(v.y - h1, v.x - h0);
    lo.y = pack2(v.w - h3, v.z - h2);
}
static __device__ __forceinline__ void mma_bf16(float* c, const uint32_t* a,
                                                uint32_t b0, uint32_t b1) {
    asm volatile("mma.sync.aligned.m16n8k16.row.col.f32.bf16.bf16.f32 "
                 "{%0,%1,%2,%3}, {%4,%5,%6,%7}, {%8,%9}, {%0,%1,%2,%3};"
                 : "+f"(c[0]), "+f"(c[1]), "+f"(c[2]), "+f"(c[3])
                 : "r"(a[0]), "r"(a[1]), "r"(a[2]), "r"(a[3]), "r"(b0), "r"(b1));
}

__global__ void __launch_bounds__(NTHREADS, 4)
sdpa_mma_kernel(const float* __restrict__ Qg_all,
                const float* __restrict__ Kg_all,
                const float* __restrict__ Vg_all,
                const int*   __restrict__ Mg_all,
                float* __restrict__ Og_all,
                float* __restrict__ Ag_all)
{
    extern __shared__ uint8_t smem[];
    uint8_t*  KH  = smem + OFF_KH;
    uint8_t*  KL  = smem + OFF_KL;
    uint8_t*  VH  = smem + OFF_VH;
    uint8_t*  VL  = smem + OFF_VL;
    uint32_t* BMw = (uint32_t*)(smem + OFF_BM);
    float* rowsum = (float*)(smem + OFF_RS);

    const int tid = threadIdx.x;
    const int w   = tid >> 5;
    const int l   = tid & 31;
    const int bh  = blockIdx.y;
    const int q0  = blockIdx.x * TQ;

    const float* Qg = Qg_all + (size_t)bh * SLEN * DHEAD;
    const float* Kg = Kg_all + (size_t)bh * SLEN * DHEAD;
    const float* Vg = Vg_all + (size_t)bh * SLEN * DHEAD;
    const int*   Mg = Mg_all + (size_t)bh * SLEN * SLEN;
    float*       Og = Og_all + (size_t)bh * SLEN * DHEAD;
    float*       Ag = Ag_all + (size_t)bh * SLEN * SLEN;

    // ================= build bit-packed mask (64 rows x 2048 bits) =================
    // 4096 32-bit words; warp handles 8 consecutive words per iteration (MLP=8).
    for (int base = 0; base < 4096; base += 32) {
        const int w0idx = base + w * 8;
        int vals[8];
#pragma unroll
        for (int j = 0; j < 8; ++j) {
            const int widx = w0idx + j;
            vals[j] = Mg[(size_t)(q0 + (widx >> 6)) * SLEN + (widx & 63) * 32 + l];
        }
#pragma unroll
        for (int j = 0; j < 8; ++j) {
            const unsigned bal = __ballot_sync(0xffffffffu, vals[j] != 0);
            const int widx = w0idx + j;
            if (l == 0) BMw[(widx >> 6) * BM_STRIDE + (widx & 63)] = bal;
        }
    }

    // ---- Q fragments straight from global (kept in regs both passes) ----
    const int rl0 = w * 16 + (l >> 2);          // local row
    const int r0  = q0 + rl0;
    uint32_t qh[4][4], ql[4][4];
    {
        const float* Qr0 = Qg + (size_t)r0 * DHEAD;
        const float* Qr8 = Qr0 + 8 * DHEAD;
#pragma unroll
        for (int ks = 0; ks < 4; ++ks) {
            const int d0 = ks * 16 + (l & 3) * 2;
            float2 q00 = *(const float2*)(Qr0 + d0);
            float2 q01 = *(const float2*)(Qr0 + d0 + 8);
            float2 q10 = *(const float2*)(Qr8 + d0);
            float2 q11 = *(const float2*)(Qr8 + d0 + 8);
            float h00x = bfr(q00.x), h00y = bfr(q00.y);
            float h10x = bfr(q10.x), h10y = bfr(q10.y);
            float h01x = bfr(q01.x), h01y = bfr(q01.y);
            float h11x = bfr(q11.x), h11y = bfr(q11.y);
            qh[ks][0] = pack2(h00y, h00x);  ql[ks][0] = pack2(q00.y - h00y, q00.x - h00x);
            qh[ks][1] = pack2(h10y, h10x);  ql[ks][1] = pack2(q10.y - h10y, q10.x - h10x);
            qh[ks][2] = pack2(h01y, h01x);  ql[ks][2] = pack2(q01.y - h01y, q01.x - h01x);
            qh[ks][3] = pack2(h11y, h11x);  ql[ks][3] = pack2(q11.y - h11y, q11.x - h11x);
        }
    }

    // per-lane swizzled bf16-tile B-fragment offsets
    uint32_t koff[4];
#pragma unroll
    for (int ks = 0; ks < 4; ++ks)
        koff[ks] = (uint32_t)(((l >> 2) * 128 + ks * 32 + (l & 3) * 4) ^ ((l >> 2) << 4));

    const int j0 = (l & 3) * 2;                 // bit offset within tile for this lane

    float oacc[8][4];
#pragma unroll
    for (int nb = 0; nb < 8; ++nb) { oacc[nb][0]=0.f; oacc[nb][1]=0.f; oacc[nb][2]=0.f; oacc[nb][3]=0.f; }
    float rs0 = 0.f, rs1 = 0.f;

    // ============================ PASS 1: rowsums + O ============================
    for (int kt = 0; kt < NKT; ++kt) {
        const int kc0 = kt * TK;

        __syncthreads();   // K/V buffers free (and bitmask build complete on kt==0)

        // ---- K tile [c][d] -> bf16 hi/lo smem ----
#pragma unroll
        for (int it = 0; it < 8; ++it) {
            const int idx = tid + it * NTHREADS;
            const int c = idx >> 4, dg = idx & 15;
            float4 v = *(const float4*)(Kg + (size_t)(kc0 + c) * DHEAD + dg * 4);
            uint2 hi, lo; split4(v, hi, lo);
            const uint32_t bo = SWZ((uint32_t)(c * 128 + dg * 8));
            *(uint2*)(KH + bo) = hi;
            *(uint2*)(KL + bo) = lo;
        }
        // ---- V tile transposed [d][k] -> bf16 hi/lo smem ----
#pragma unroll
        for (int it = 0; it < 8; ++it) {
            const int idx = tid + it * NTHREADS;
            const int d = idx & 63, kg = idx >> 6;
            const float* vp = Vg + (size_t)(kc0 + kg * 4) * DHEAD + d;
            float4 v = make_float4(vp[0], vp[DHEAD], vp[2 * DHEAD], vp[3 * DHEAD]);
            uint2 hi, lo; split4(v, hi, lo);
            const uint32_t bo = SWZ((uint32_t)(d * 128 + kg * 8));
            *(uint2*)(VH + bo) = hi;
            *(uint2*)(VL + bo) = lo;
        }
        __syncthreads();

        // ---- S = Qh Kh + Qh Kl + Ql Kh ----
        float sacc[8][4];
#pragma unroll
        for (int nb = 0; nb < 8; ++nb) { sacc[nb][0]=0.f; sacc[nb][1]=0.f; sacc[nb][2]=0.f; sacc[nb][3]=0.f; }
#pragma unroll
        for (int ks = 0; ks < 4; ++ks) {
#pragma unroll
            for (int nb = 0; nb < 8; ++nb) {
                const uint32_t o = koff[ks] + nb * 1024;
                const uint32_t kh0 = *(const uint32_t*)(KH + o);
                const uint32_t kh1 = *(const uint32_t*)(KH + (o ^ 16));
                const uint32_t kl0 = *(const uint32_t*)(KL + o);
                const uint32_t kl1 = *(const uint32_t*)(KL + (o ^ 16));
                mma_bf16(sacc[nb], qh[ks], kh0, kh1);
                mma_bf16(sacc[nb], qh[ks], kl0, kl1);
                mma_bf16(sacc[nb], ql[ks], kh0, kh1);
            }
        }

        // ---- mask bits from smem, exp, rowsum, P fragments ----
        uint64_t bits0, bits1;
        {
            uint2 b0 = *(const uint2*)(BMw + rl0 * BM_STRIDE + kt * 2);
            uint2 b1 = *(const uint2*)(BMw + (rl0 + 8) * BM_STRIDE + kt * 2);
            bits0 = ((uint64_t)b0.y << 32 | b0.x) >> j0;
            bits1 = ((uint64_t)b1.y << 32 | b1.x) >> j0;
        }
        uint32_t phi[4][4], plo[4][4];
#pragma unroll
        for (int nb = 0; nb < 8; ++nb) {
            const uint32_t s0 = (uint32_t)(bits0 >> (nb * 8));
            const uint32_t s1 = (uint32_t)(bits1 >> (nb * 8));
            float p0 = (s0 & 1) ? __expf(sacc[nb][0] * 0.125f) : 0.f;
            float p1 = (s0 & 2) ? __expf(sacc[nb][1] * 0.125f) : 0.f;
            float p2 = (s1 & 1) ? __expf(sacc[nb][2] * 0.125f) : 0.f;
            float p3 = (s1 & 2) ? __expf(sacc[nb][3] * 0.125f) : 0.f;
            rs0 += p0 + p1;
            rs1 += p2 + p3;
            const float h0 = bfr(p0), h1 = bfr(p1), h2 = bfr(p2), h3 = bfr(p3);
            const int j = nb >> 1, hf = (nb & 1) * 2;
            phi[j][hf + 0] = pack2(h1, h0);
            phi[j][hf + 1] = pack2(h3, h2);
            plo[j][hf + 0] = pack2(p1 - h1, p0 - h0);
            plo[j][hf + 1] = pack2(p3 - h3, p2 - h2);
        }

        // ---- O += Ph Vh + Ph Vl + Pl Vh ----
#pragma unroll
        for (int j = 0; j < 4; ++j) {
#pragma unroll
            for (int nb = 0; nb < 8; ++nb) {
                const uint32_t o = koff[j] + nb * 1024;
                const uint32_t vh0 = *(const uint32_t*)(VH + o);
                const uint32_t vh1 = *(const uint32_t*)(VH + (o ^ 16));
                const uint32_t vl0 = *(const uint32_t*)(VL + o);
                const uint32_t vl1 = *(const uint32_t*)(VL + (o ^ 16));
                mma_bf16(oacc[nb], phi[j], vh0, vh1);
                mma_bf16(oacc[nb], phi[j], vl0, vl1);
                mma_bf16(oacc[nb], plo[j], vh0, vh1);
            }
        }
    }

    // ---- row sums: reduce 4 lanes per row, invert ----
    rs0 += __shfl_xor_sync(0xffffffffu, rs0, 1);
    rs0 += __shfl_xor_sync(0xffffffffu, rs0, 2);
    rs1 += __shfl_xor_sync(0xffffffffu, rs1, 1);
    rs1 += __shfl_xor_sync(0xffffffffu, rs1, 2);
    if ((l & 3) == 0) {
        rowsum[rl0]     = rs0;
        rowsum[rl0 + 8] = rs1;
    }
    __syncthreads();
    if (tid < TQ) rowsum[tid] = 1.0f / rowsum[tid];
    __syncthreads();

    const float inv0 = rowsum[rl0];
    const float inv1 = rowsum[rl0 + 8];

    // ---- write normalized O (frees oacc for pass 2) ----
    {
        float* or0 = Og + (size_t)r0 * DHEAD + (l & 3) * 2;
        float* or8 = or0 + 8 * DHEAD;
#pragma unroll
        for (int nb = 0; nb < 8; ++nb) {
            *(float2*)(or0 + nb * 8) = make_float2(oacc[nb][0] * inv0, oacc[nb][1] * inv0);
            *(float2*)(or8 + nb * 8) = make_float2(oacc[nb][2] * inv1, oacc[nb][3] * inv1);
        }
    }

    // ============================ PASS 2: normalized attention ============================
    float* ab0 = Ag + (size_t)r0 * SLEN + (l & 3) * 2;

    for (int kt = 0; kt < NKT; ++kt) {
        const int kc0 = kt * TK;

        __syncthreads();   // K buffers free

        // ---- K tile [c][d] -> bf16 hi/lo smem ----
#pragma unroll
        for (int it = 0; it < 8; ++it) {
            const int idx = tid + it * NTHREADS;
            const int c = idx >> 4, dg = idx & 15;
            float4 v = *(const float4*)(Kg + (size_t)(kc0 + c) * DHEAD + dg * 4);
            uint2 hi, lo; split4(v, hi, lo);
            const uint32_t bo = SWZ((uint32_t)(c * 128 + dg * 8));
            *(uint2*)(KH + bo) = hi;
            *(uint2*)(KL + bo) = lo;
        }
        __syncthreads();

        // ---- S = Qh Kh + Qh Kl + Ql Kh ----
        float sacc[8][4];
#pragma unroll
        for (int nb = 0; nb < 8; ++nb) { sacc[nb][0]=0.f; sacc[nb][1]=0.f; sacc[nb][2]=0.f; sacc[nb][3]=0.f; }
#pragma unroll
        for (int ks = 0; ks < 4; ++ks) {
#pragma unroll
            for (int nb = 0; nb < 8; ++nb) {
                const uint32_t o = koff[ks] + nb * 1024;
                const uint32_t kh0 = *(const uint32_t*)(KH + o);
                const uint32_t kh1 = *(const uint32_t*)(KH + (o ^ 16));
                const uint32_t kl0 = *(const uint32_t*)(KL + o);
                const uint32_t kl1 = *(const uint32_t*)(KL + (o ^ 16));
                mma_bf16(sacc[nb], qh[ks], kh0, kh1);
                mma_bf16(sacc[nb], qh[ks], kl0, kl1);
                mma_bf16(sacc[nb], ql[ks], kh0, kh1);
            }
        }

        // ---- exp * inv, write normalized attention once ----
        uint64_t bits0, bits1;
        {
            uint2 b0 = *(const uint2*)(BMw + rl0 * BM_STRIDE + kt * 2);
            uint2 b1 = *(const uint2*)(BMw + (rl0 + 8) * BM_STRIDE + kt * 2);
            bits0 = ((uint64_t)b0.y << 32 | b0.x) >> j0;
            bits1 = ((uint64_t)b1.y << 32 | b1.x) >> j0;
        }
        float* ar0 = ab0 + kc0;
        float* ar8 = ar0 + 8 * SLEN;
#pragma unroll
        for (int nb = 0; nb < 8; ++nb) {
            const uint32_t s0 = (uint32_t)(bits0 >> (nb * 8));
            const uint32_t s1 = (uint32_t)(bits1 >> (nb * 8));
            float p0 = (s0 & 1) ? __expf(sacc[nb][0] * 0.125f) * inv0 : 0.f;
            float p1 = (s0 & 2) ? __expf(sacc[nb][1] * 0.125f) * inv0 : 0.f;
            float p2 = (s1 & 1) ? __expf(sacc[nb][2] * 0.125f) * inv1 : 0.f;
            float p3 = (s1 & 2) ? __expf(sacc[nb][3] * 0.125f) * inv1 : 0.f;
            *(float2*)(ar0 + nb * 8) = make_float2(p0, p1);
            *(float2*)(ar8 + nb * 8) = make_float2(p2, p3);
        }
    }
}

extern "C" void kernel_launch(void* const* d_in, const int* in_sizes, int n_in,
                              void* d_out, int out_size)
{
    const float* Q    = (const float*)d_in[0];
    const float* K    = (const float*)d_in[1];
    const float* V    = (const float*)d_in[2];
    const int*   mask = (const int*)d_in[3];
    (void)in_sizes; (void)n_in; (void)out_size;

    float* out  = (float*)d_out;
    float* attn = out + OUT_ELEMS;

    static int configured = 0;
    if (!configured) {
        cudaFuncSetAttribute(sdpa_mma_kernel,
                             cudaFuncAttributeMaxDynamicSharedMemorySize, SMEM_BYTES);
        configured = 1;
    }

    dim3 grid(SLEN / TQ, BHN);   // (32, 64)
    sdpa_mma_kernel<<<grid, NTHREADS, SMEM_BYTES>>>(Q, K, V, mask, out, attn);
}

// round 8
// speedup vs baseline: 1.3325x; 1.1013x over previous
#include <cuda_runtime.h>
#include <cuda_bf16.h>
#include <cstdint>

#define SLEN    2048
#define DHEAD   64
#define BHN     64
#define TQ      128
#define TK      64
#define NTHREADS 256
#define NKT     (SLEN / TK)
#define OUT_ELEMS ((size_t)BHN * SLEN * DHEAD)   // 8,388,608

#define PITCH   144                     // bytes per 64-element bf16 row (bank-safe for ldmatrix)
#define BUF_B   (64 * PITCH)            // 9216 B per tile buffer

// ---- dynamic smem layout (bytes) ----
#define OFF_KH 0
#define OFF_KL (BUF_B)
#define OFF_VH (2 * BUF_B)
#define OFF_VL (3 * BUF_B)
#define OFF_BM (4 * BUF_B)              // 128 rows x 68 words = 34816 B
#define OFF_RS (OFF_BM + 34816)         // 128 floats
#define SMEM_BYTES (OFF_RS + 512)
#define BM_STRIDE 68

static __device__ __forceinline__ uint32_t pack2(float hi, float lo) {
    uint32_t r;
    asm("cvt.rn.bf16x2.f32 %0, %1, %2;" : "=r"(r) : "f"(hi), "f"(lo));
    return r;
}
static __device__ __forceinline__ float bfr(float x) {
    return __bfloat162float(__float2bfloat16(x));
}
static __device__ __forceinline__ void split4(float4 v, uint2& hi, uint2& lo) {
    float h0 = bfr(v.x), h1 = bfr(v.y), h2 = bfr(v.z), h3 = bfr(v.w);
    hi.x = pack2(h1, h0);
    hi.y = pack2(h3, h2);
    lo.x = pack2(v.y - h1, v.x - h0);
    lo.y = pack2(v.w - h3, v.z - h2);
}
static __device__ __forceinline__ uint32_t smem_u32(const void* p) {
    uint32_t a;
    asm("{ .reg .u64 t; cvta.to.shared.u64 t, %1; cvt.u32.u64 %0, t; }" : "=r"(a) : "l"(p));
    return a;
}
static __device__ __forceinline__ void mma_bf16(float* c, const uint32_t* a,
                                                uint32_t b0, uint32_t b1) {
    asm volatile("mma.sync.aligned.m16n8k16.row.col.f32.bf16.bf16.f32 "
                 "{%0,%1,%2,%3}, {%4,%5,%6,%7}, {%8,%9}, {%0,%1,%2,%3};"
                 : "+f"(c[0]), "+f"(c[1]), "+f"(c[2]), "+f"(c[3])
                 : "r"(a[0]), "r"(a[1]), "r"(a[2]), "r"(a[3]), "r"(b0), "r"(b1));
}
static __device__ __forceinline__ void ldsm4(uint32_t& r0, uint32_t& r1,
                                             uint32_t& r2, uint32_t& r3, uint32_t addr) {
    asm volatile("ldmatrix.sync.aligned.m8n8.x4.shared.b16 {%0,%1,%2,%3}, [%4];"
                 : "=r"(r0), "=r"(r1), "=r"(r2), "=r"(r3) : "r"(addr));
}
static __device__ __forceinline__ void ldsm4t(uint32_t& r0, uint32_t& r1,
                                              uint32_t& r2, uint32_t& r3, uint32_t addr) {
    asm volatile("ldmatrix.sync.aligned.m8n8.x4.trans.shared.b16 {%0,%1,%2,%3}, [%4];"
                 : "=r"(r0), "=r"(r1), "=r"(r2), "=r"(r3) : "r"(addr));
}

__global__ void __launch_bounds__(NTHREADS, 2)
sdpa_mma_kernel(const float* __restrict__ Qg_all,
                const float* __restrict__ Kg_all,
                const float* __restrict__ Vg_all,
                const int*   __restrict__ Mg_all,
                float* __restrict__ Og_all,
                float* __restrict__ Ag_all)
{
    extern __shared__ uint8_t smem[];
    const uint32_t smb = smem_u32(smem);
    uint32_t* BMw = (uint32_t*)(smem + OFF_BM);
    float* rowsum = (float*)(smem + OFF_RS);

    const int tid = threadIdx.x;
    const int w   = tid >> 5;
    const int l   = tid & 31;
    const int bh  = blockIdx.y;
    const int q0  = blockIdx.x * TQ;

    const float* Qg = Qg_all + (size_t)bh * SLEN * DHEAD;
    const float* Kg = Kg_all + (size_t)bh * SLEN * DHEAD;
    const float* Vg = Vg_all + (size_t)bh * SLEN * DHEAD;
    const int*   Mg = Mg_all + (size_t)bh * SLEN * SLEN;
    float*       Og = Og_all + (size_t)bh * SLEN * DHEAD;
    float*       Ag = Ag_all + (size_t)bh * SLEN * SLEN;

    // ================= bit-packed mask: 128 rows x 2048 bits =================
    // 8192 words; 8 warps x 8 words per iteration.
    for (int base = 0; base < 8192; base += 64) {
        const int w0idx = base + w * 8;
        int vals[8];
#pragma unroll
        for (int j = 0; j < 8; ++j) {
            const int widx = w0idx + j;
            vals[j] = Mg[(size_t)(q0 + (widx >> 6)) * SLEN + (widx & 63) * 32 + l];
        }
#pragma unroll
        for (int j = 0; j < 8; ++j) {
            const unsigned bal = __ballot_sync(0xffffffffu, vals[j] != 0);
            const int widx = w0idx + j;
            if (l == 0) BMw[(widx >> 6) * BM_STRIDE + (widx & 63)] = bal;
        }
    }

    // ---- Q fragments straight from global (kept in regs both passes) ----
    const int rl0 = w * 16 + (l >> 2);          // local row 0..127
    const int r0  = q0 + rl0;
    uint32_t qh[4][4], ql[4][4];
    {
        const float* Qr0 = Qg + (size_t)r0 * DHEAD;
        const float* Qr8 = Qr0 + 8 * DHEAD;
#pragma unroll
        for (int ks = 0; ks < 4; ++ks) {
            const int d0 = ks * 16 + (l & 3) * 2;
            float2 q00 = *(const float2*)(Qr0 + d0);
            float2 q01 = *(const float2*)(Qr0 + d0 + 8);
            float2 q10 = *(const float2*)(Qr8 + d0);
            float2 q11 = *(const float2*)(Qr8 + d0 + 8);
            float h00x = bfr(q00.x), h00y = bfr(q00.y);
            float h10x = bfr(q10.x), h10y = bfr(q10.y);
            float h01x = bfr(q01.x), h01y = bfr(q01.y);
            float h11x = bfr(q11.x), h11y = bfr(q11.y);
            qh[ks][0] = pack2(h00y, h00x);  ql[ks][0] = pack2(q00.y - h00y, q00.x - h00x);
            qh[ks][1] = pack2(h10y, h10x);  ql[ks][1] = pack2(q10.y - h10y, q10.x - h10x);
            qh[ks][2] = pack2(h01y, h01x);  ql[ks][2] = pack2(q01.y - h01y, q01.x - h01x);
            qh[ks][3] = pack2(h11y, h11x);  ql[ks][3] = pack2(q11.y - h11y, q11.x - h11x);
        }
    }

    // ---- per-lane ldmatrix base addresses ----
    const int mslot = l >> 3, mrow = l & 7;
    // K buffers (n-major): slots = (n8 = 2np + m>>1, k8 = 2ks + m&1)
    const uint32_t laneK = (uint32_t)((((mslot >> 1) * 8) + mrow) * PITCH + (mslot & 1) * 16);
    // V buffers (k-major, trans): slots = (k8 = 2j + m&1, n8 = 2np + m>>1)
    const uint32_t laneV = (uint32_t)((((mslot & 1) * 8) + mrow) * PITCH + (mslot >> 1) * 16);
    const uint32_t aKH = smb + OFF_KH + laneK, aKL = smb + OFF_KL + laneK;
    const uint32_t aVH = smb + OFF_VH + laneV, aVL = smb + OFF_VL + laneV;

    const int j0 = (l & 3) * 2;                 // bitmask lane offset

    float oacc[8][4];
#pragma unroll
    for (int nb = 0; nb < 8; ++nb) { oacc[nb][0]=0.f; oacc[nb][1]=0.f; oacc[nb][2]=0.f; oacc[nb][3]=0.f; }
    float rs0 = 0.f, rs1 = 0.f;

    // ============================ PASS 1: rowsums + O ============================
    for (int kt = 0; kt < NKT; ++kt) {

        __syncthreads();   // buffers free (bitmask complete on kt==0)

        // ---- K tile [c][d] -> bf16 hi/lo (pitch-144 rows) ----
#pragma unroll
        for (int it = 0; it < 4; ++it) {
            const int idx = tid + it * NTHREADS;         // 1024 float4 groups
            const int c = idx >> 4, dg = idx & 15;
            float4 v = *(const float4*)(Kg + (size_t)(kt * TK + c) * DHEAD + dg * 4);
            uint2 hi, lo; split4(v, hi, lo);
            const uint32_t bo = (uint32_t)(c * PITCH + dg * 8);
            *(uint2*)(smem + OFF_KH + bo) = hi;
            *(uint2*)(smem + OFF_KL + bo) = lo;
        }
        // ---- V tile [k][d] natural layout -> bf16 hi/lo ----
#pragma unroll
        for (int it = 0; it < 4; ++it) {
            const int idx = tid + it * NTHREADS;
            const int k = idx >> 4, dg = idx & 15;
            float4 v = *(const float4*)(Vg + (size_t)(kt * TK + k) * DHEAD + dg * 4);
            uint2 hi, lo; split4(v, hi, lo);
            const uint32_t bo = (uint32_t)(k * PITCH + dg * 8);
            *(uint2*)(smem + OFF_VH + bo) = hi;
            *(uint2*)(smem + OFF_VL + bo) = lo;
        }
        __syncthreads();

        // ---- S = Qh Kh + Qh Kl + Ql Kh (ldmatrix B-frags) ----
        float sacc[8][4];
#pragma unroll
        for (int nb = 0; nb < 8; ++nb) { sacc[nb][0]=0.f; sacc[nb][1]=0.f; sacc[nb][2]=0.f; sacc[nb][3]=0.f; }
#pragma unroll
        for (int ks = 0; ks < 4; ++ks) {
#pragma unroll
            for (int np = 0; np < 4; ++np) {
                const uint32_t off = (uint32_t)(np * 16 * PITCH + ks * 32);
                uint32_t h0, h1, h2, h3, e0, e1, e2, e3;
                ldsm4(h0, h1, h2, h3, aKH + off);
                ldsm4(e0, e1, e2, e3, aKL + off);
                mma_bf16(sacc[np * 2],     qh[ks], h0, h1);
                mma_bf16(sacc[np * 2],     qh[ks], e0, e1);
                mma_bf16(sacc[np * 2],     ql[ks], h0, h1);
                mma_bf16(sacc[np * 2 + 1], qh[ks], h2, h3);
                mma_bf16(sacc[np * 2 + 1], qh[ks], e2, e3);
                mma_bf16(sacc[np * 2 + 1], ql[ks], h2, h3);
            }
        }

        // ---- mask bits, exp, rowsum, P fragments ----
        uint64_t bits0, bits1;
        {
            uint2 b0 = *(const uint2*)(BMw + rl0 * BM_STRIDE + kt * 2);
            uint2 b1 = *(const uint2*)(BMw + (rl0 + 8) * BM_STRIDE + kt * 2);
            bits0 = ((uint64_t)b0.y << 32 | b0.x) >> j0;
            bits1 = ((uint64_t)b1.y << 32 | b1.x) >> j0;
        }
        uint32_t phi[4][4], plo[4][4];
#pragma unroll
        for (int nb = 0; nb < 8; ++nb) {
            const uint32_t s0 = (uint32_t)(bits0 >> (nb * 8));
            const uint32_t s1 = (uint32_t)(bits1 >> (nb * 8));
            float p0 = (s0 & 1) ? __expf(sacc[nb][0] * 0.125f) : 0.f;
            float p1 = (s0 & 2) ? __expf(sacc[nb][1] * 0.125f) : 0.f;
            float p2 = (s1 & 1) ? __expf(sacc[nb][2] * 0.125f) : 0.f;
            float p3 = (s1 & 2) ? __expf(sacc[nb][3] * 0.125f) : 0.f;
            rs0 += p0 + p1;
            rs1 += p2 + p3;
            const float h0 = bfr(p0), h1 = bfr(p1), h2 = bfr(p2), h3 = bfr(p3);
            const int j = nb >> 1, hf = (nb & 1) * 2;
            phi[j][hf + 0] = pack2(h1, h0);
            phi[j][hf + 1] = pack2(h3, h2);
            plo[j][hf + 0] = pack2(p1 - h1, p0 - h0);
            plo[j][hf + 1] = pack2(p3 - h3, p2 - h2);
        }

        // ---- O += Ph Vh + Ph Vl + Pl Vh (ldmatrix.trans B-frags) ----
#pragma unroll
        for (int j = 0; j < 4; ++j) {
#pragma unroll
            for (int np = 0; np < 4; ++np) {
                const uint32_t off = (uint32_t)(j * 16 * PITCH + np * 32);
                uint32_t h0, h1, h2, h3, e0, e1, e2, e3;
                ldsm4t(h0, h1, h2, h3, aVH + off);
                ldsm4t(e0, e1, e2, e3, aVL + off);
                mma_bf16(oacc[np * 2],     phi[j], h0, h1);
                mma_bf16(oacc[np * 2],     phi[j], e0, e1);
                mma_bf16(oacc[np * 2],     plo[j], h0, h1);
                mma_bf16(oacc[np * 2 + 1], phi[j], h2, h3);
                mma_bf16(oacc[np * 2 + 1], phi[j], e2, e3);
                mma_bf16(oacc[np * 2 + 1], plo[j], h2, h3);
            }
        }
    }

    // ---- row sums: reduce 4 lanes per row, invert ----
    rs0 += __shfl_xor_sync(0xffffffffu, rs0, 1);
    rs0 += __shfl_xor_sync(0xffffffffu, rs0, 2);
    rs1 += __shfl_xor_sync(0xffffffffu, rs1, 1);
    rs1 += __shfl_xor_sync(0xffffffffu, rs1, 2);
    if ((l & 3) == 0) {
        rowsum[rl0]     = rs0;
        rowsum[rl0 + 8] = rs1;
    }
    __syncthreads();
    if (tid < TQ) rowsum[tid] = 1.0f / rowsum[tid];
    __syncthreads();

    const float inv0 = rowsum[rl0];
    const float inv1 = rowsum[rl0 + 8];

    // ---- write normalized O ----
    {
        float* or0 = Og + (size_t)r0 * DHEAD + (l & 3) * 2;
        float* or8 = or0 + 8 * DHEAD;
#pragma unroll
        for (int nb = 0; nb < 8; ++nb) {
            *(float2*)(or0 + nb * 8) = make_float2(oacc[nb][0] * inv0, oacc[nb][1] * inv0);
            *(float2*)(or8 + nb * 8) = make_float2(oacc[nb][2] * inv1, oacc[nb][3] * inv1);
        }
    }

    // ============================ PASS 2: normalized attention ============================
    float* ab0 = Ag + (size_t)r0 * SLEN + (l & 3) * 2;

    for (int kt = 0; kt < NKT; ++kt) {

        __syncthreads();

        // ---- K tile reload/convert ----
#pragma unroll
        for (int it = 0; it < 4; ++it) {
            const int idx = tid + it * NTHREADS;
            const int c = idx >> 4, dg = idx & 15;
            float4 v = *(const float4*)(Kg + (size_t)(kt * TK + c) * DHEAD + dg * 4);
            uint2 hi, lo; split4(v, hi, lo);
            const uint32_t bo = (uint32_t)(c * PITCH + dg * 8);
            *(uint2*)(smem + OFF_KH + bo) = hi;
            *(uint2*)(smem + OFF_KL + bo) = lo;
        }
        __syncthreads();

        // ---- S recompute ----
        float sacc[8][4];
#pragma unroll
        for (int nb = 0; nb < 8; ++nb) { sacc[nb][0]=0.f; sacc[nb][1]=0.f; sacc[nb][2]=0.f; sacc[nb][3]=0.f; }
#pragma unroll
        for (int ks = 0; ks < 4; ++ks) {
#pragma unroll
            for (int np = 0; np < 4; ++np) {
                const uint32_t off = (uint32_t)(np * 16 * PITCH + ks * 32);
                uint32_t h0, h1, h2, h3, e0, e1, e2, e3;
                ldsm4(h0, h1, h2, h3, aKH + off);
                ldsm4(e0, e1, e2, e3, aKL + off);
                mma_bf16(sacc[np * 2],     qh[ks], h0, h1);
                mma_bf16(sacc[np * 2],     qh[ks], e0, e1);
                mma_bf16(sacc[np * 2],     ql[ks], h0, h1);
                mma_bf16(sacc[np * 2 + 1], qh[ks], h2, h3);
                mma_bf16(sacc[np * 2 + 1], qh[ks], e2, e3);
                mma_bf16(sacc[np * 2 + 1], ql[ks], h2, h3);
            }
        }

        // ---- exp * inv, write normalized attention once ----
        uint64_t bits0, bits1;
        {
            uint2 b0 = *(const uint2*)(BMw + rl0 * BM_STRIDE + kt * 2);
            uint2 b1 = *(const uint2*)(BMw + (rl0 + 8) * BM_STRIDE + kt * 2);
            bits0 = ((uint64_t)b0.y << 32 | b0.x) >> j0;
            bits1 = ((uint64_t)b1.y << 32 | b1.x) >> j0;
        }
        float* ar0 = ab0 + kt * TK;
        float* ar8 = ar0 + 8 * SLEN;
#pragma unroll
        for (int nb = 0; nb < 8; ++nb) {
            const uint32_t s0 = (uint32_t)(bits0 >> (nb * 8));
            const uint32_t s1 = (uint32_t)(bits1 >> (nb * 8));
            float p0 = (s0 & 1) ? __expf(sacc[nb][0] * 0.125f) * inv0 : 0.f;
            float p1 = (s0 & 2) ? __expf(sacc[nb][1] * 0.125f) * inv0 : 0.f;
            float p2 = (s1 & 1) ? __expf(sacc[nb][2] * 0.125f) * inv1 : 0.f;
            float p3 = (s1 & 2) ? __expf(sacc[nb][3] * 0.125f) * inv1 : 0.f;
            *(float2*)(ar0 + nb * 8) = make_float2(p0, p1);
            *(float2*)(ar8 + nb * 8) = make_float2(p2, p3);
        }
    }
}

extern "C" void kernel_launch(void* const* d_in, const int* in_sizes, int n_in,
                              void* d_out, int out_size)
{
    const float* Q    = (const float*)d_in[0];
    const float* K    = (const float*)d_in[1];
    const float* V    = (const float*)d_in[2];
    const int*   mask = (const int*)d_in[3];
    (void)in_sizes; (void)n_in; (void)out_size;

    float* out  = (float*)d_out;
    float* attn = out + OUT_ELEMS;

    static int configured = 0;
    if (!configured) {
        cudaFuncSetAttribute(sdpa_mma_kernel,
                             cudaFuncAttributeMaxDynamicSharedMemorySize, SMEM_BYTES);
        configured = 1;
    }

    dim3 grid(SLEN / TQ, BHN);   // (16, 64)
    sdpa_mma_kernel<<<grid, NTHREADS, SMEM_BYTES>>>(Q, K, V, mask, out, attn);
}

// round 9
// speedup vs baseline: 1.3703x; 1.0284x over previous
#include <cuda_runtime.h>
#include <cstdint>

#define SLEN    2048
#define DHEAD   64
#define BHN     64
#define TQ      128
#define TK      64
#define NTHREADS 256
#define NKT     (SLEN / TK)
#define OUT_ELEMS ((size_t)BHN * SLEN * DHEAD)   // 8,388,608

#define PITCHB  288                     // bytes per 64-f32 row (72 words, bank-safe)
#define KBUF_B  (64 * PITCHB)           // 18432
#define BUF_B   (2 * KBUF_B)            // K + V per stage = 36864

// ---- dynamic smem layout (bytes) ----
#define OFF_BM  (2 * BUF_B)             // 73728; 128 rows x 68 words = 34816
#define OFF_RS  (OFF_BM + 34816)        // 108544
#define SMEM_BYTES (OFF_RS + 512)       // 109056 -> 2 CTAs/SM
#define BM_STRIDE 68

static __device__ __forceinline__ uint32_t smem_u32(const void* p) {
    uint32_t a;
    asm("{ .reg .u64 t; cvta.to.shared.u64 t, %1; cvt.u32.u64 %0, t; }" : "=r"(a) : "l"(p));
    return a;
}
static __device__ __forceinline__ void cp16(uint32_t sm, const void* g) {
    asm volatile("cp.async.cg.shared.global [%0], [%1], 16;" :: "r"(sm), "l"(g));
}
static __device__ __forceinline__ uint32_t f2tf(float f) {
    uint32_t u;
    asm("cvt.rna.tf32.f32 %0, %1;" : "=r"(u) : "f"(f));
    return u;
}
static __device__ __forceinline__ void mma_tf32(float* c, const uint32_t* a,
                                                uint32_t b0, uint32_t b1) {
    asm volatile("mma.sync.aligned.m16n8k8.row.col.f32.tf32.tf32.f32 "
                 "{%0,%1,%2,%3}, {%4,%5,%6,%7}, {%8,%9}, {%0,%1,%2,%3};"
                 : "+f"(c[0]), "+f"(c[1]), "+f"(c[2]), "+f"(c[3])
                 : "r"(a[0]), "r"(a[1]), "r"(a[2]), "r"(a[3]), "r"(b0), "r"(b1));
}
static __device__ __forceinline__ uint32_t lds32(uint32_t a) {
    uint32_t v;
    asm volatile("ld.shared.b32 %0, [%1];" : "=r"(v) : "r"(a));
    return v;
}

__global__ void __launch_bounds__(NTHREADS, 2)
sdpa_tf32_kernel(const float* __restrict__ Qg_all,
                 const float* __restrict__ Kg_all,
                 const float* __restrict__ Vg_all,
                 const int*   __restrict__ Mg_all,
                 float* __restrict__ Og_all,
                 float* __restrict__ Ag_all)
{
    extern __shared__ uint8_t smem[];
    const uint32_t smb = smem_u32(smem);
    uint32_t* BMw = (uint32_t*)(smem + OFF_BM);
    float* rowsum = (float*)(smem + OFF_RS);

    const int tid = threadIdx.x;
    const int w   = tid >> 5;
    const int l   = tid & 31;
    const int bh  = blockIdx.y;
    const int q0  = blockIdx.x * TQ;

    const float* Qg = Qg_all + (size_t)bh * SLEN * DHEAD;
    const float* Kg = Kg_all + (size_t)bh * SLEN * DHEAD;
    const float* Vg = Vg_all + (size_t)bh * SLEN * DHEAD;
    const int*   Mg = Mg_all + (size_t)bh * SLEN * SLEN;
    float*       Og = Og_all + (size_t)bh * SLEN * DHEAD;
    float*       Ag = Ag_all + (size_t)bh * SLEN * SLEN;

    // ---- cp.async issue: K tile natural rows, V tile with k-row permutation ----
    auto issue_kv = [&](int kt, int b) {
        if (kt < NKT) {
            const float* Kt = Kg + (size_t)kt * TK * DHEAD;
            const float* Vt = Vg + (size_t)kt * TK * DHEAD;
            const uint32_t base = smb + b * BUF_B;
#pragma unroll
            for (int j = 0; j < 4; ++j) {
                const int idx = tid + j * NTHREADS;      // 0..1023 16B chunks
                const int row = idx >> 4, ch = idx & 15;
                cp16(base + row * PITCHB + ch * 16, Kt + row * DHEAD + ch * 4);
                const int jj = row & 7;
                const int pr = (row & ~7) | ((jj & 1) ? 4 + (jj >> 1) : (jj >> 1));
                cp16(base + KBUF_B + pr * PITCHB + ch * 16, Vt + row * DHEAD + ch * 4);
            }
        }
        asm volatile("cp.async.commit_group;" ::: "memory");
    };
    auto issue_k = [&](int kt, int b) {    // pass 2: K only
        if (kt < NKT) {
            const float* Kt = Kg + (size_t)kt * TK * DHEAD;
            const uint32_t base = smb + b * BUF_B;
#pragma unroll
            for (int j = 0; j < 4; ++j) {
                const int idx = tid + j * NTHREADS;
                const int row = idx >> 4, ch = idx & 15;
                cp16(base + row * PITCHB + ch * 16, Kt + row * DHEAD + ch * 4);
            }
        }
        asm volatile("cp.async.commit_group;" ::: "memory");
    };
    // in-place RNA tf32 normalization sweep over nwords*4 bytes of one buffer
    auto tf32_sweep = [&](int b, int nf4) {
        const uint32_t a0 = smb + b * BUF_B + tid * 16;
        for (int j = 0; j < nf4; ++j) {
            const uint32_t ad = a0 + j * (NTHREADS * 16);
            uint32_t x, y, z, t;
            asm volatile("ld.shared.v4.b32 {%0,%1,%2,%3}, [%4];"
                         : "=r"(x), "=r"(y), "=r"(z), "=r"(t) : "r"(ad));
            x = f2tf(__uint_as_float(x)); y = f2tf(__uint_as_float(y));
            z = f2tf(__uint_as_float(z)); t = f2tf(__uint_as_float(t));
            asm volatile("st.shared.v4.b32 [%0], {%1,%2,%3,%4};"
                         :: "r"(ad), "r"(x), "r"(y), "r"(z), "r"(t));
        }
    };

    // prologue: start streaming tiles 0,1 while we build the bitmask
    issue_kv(0, 0);
    issue_kv(1, 1);

    // ================= bit-packed mask: 128 rows x 2048 bits =================
    for (int base = 0; base < 8192; base += 64) {
        const int w0idx = base + w * 8;
        int vals[8];
#pragma unroll
        for (int j = 0; j < 8; ++j) {
            const int widx = w0idx + j;
            vals[j] = Mg[(size_t)(q0 + (widx >> 6)) * SLEN + (widx & 63) * 32 + l];
        }
#pragma unroll
        for (int j = 0; j < 8; ++j) {
            const unsigned bal = __ballot_sync(0xffffffffu, vals[j] != 0);
            const int widx = w0idx + j;
            if (l == 0) BMw[(widx >> 6) * BM_STRIDE + (widx & 63)] = bal;
        }
    }

    // ---- Q A-fragments (tf32), kept in regs for both passes ----
    const int rl0 = w * 16 + (l >> 2);
    const int r0  = q0 + rl0;
    uint32_t qa[8][4];
    {
        const float* Qr0 = Qg + (size_t)r0 * DHEAD;
#pragma unroll
        for (int s = 0; s < 8; ++s) {
            const int d0 = s * 8 + (l & 3);
            qa[s][0] = f2tf(Qr0[d0]);
            qa[s][1] = f2tf(Qr0[8 * DHEAD + d0]);
            qa[s][2] = f2tf(Qr0[d0 + 4]);
            qa[s][3] = f2tf(Qr0[8 * DHEAD + d0 + 4]);
        }
    }

    const uint32_t laneK = (uint32_t)((l >> 2) * PITCHB + (l & 3) * 4);
    const uint32_t laneV = (uint32_t)(KBUF_B + (l & 3) * PITCHB + (l >> 2) * 4);
    const int j0 = (l & 3) * 2;

    float oacc[8][4];
#pragma unroll
    for (int nb = 0; nb < 8; ++nb) { oacc[nb][0]=0.f; oacc[nb][1]=0.f; oacc[nb][2]=0.f; oacc[nb][3]=0.f; }
    float rs0 = 0.f, rs1 = 0.f;

    // ============================ PASS 1: rowsums + O ============================
    for (int kt = 0; kt < NKT; ++kt) {
        const int b = kt & 1;
        const uint32_t bufb = smb + b * BUF_B;

        asm volatile("cp.async.wait_group 1;" ::: "memory");
        __syncthreads();
        tf32_sweep(b, 9);               // K+V: 36864 B = 2304 f4 = 9/thread
        __syncthreads();

        // ---- S = Q K^T (tf32) ----
        float sacc[8][4];
#pragma unroll
        for (int nb = 0; nb < 8; ++nb) { sacc[nb][0]=0.f; sacc[nb][1]=0.f; sacc[nb][2]=0.f; sacc[nb][3]=0.f; }
        const uint32_t aK = bufb + laneK;
#pragma unroll
        for (int s = 0; s < 8; ++s) {
#pragma unroll
            for (int nb = 0; nb < 8; ++nb) {
                const uint32_t ad = aK + nb * (8 * PITCHB) + s * 32;
                const uint32_t b0 = lds32(ad);
                const uint32_t b1 = lds32(ad + 16);
                mma_tf32(sacc[nb], qa[s], b0, b1);
            }
        }

        // ---- mask bits, exp, rowsum, P->A frags ({c0,c2,c1,c3} renaming) ----
        uint64_t bits0, bits1;
        {
            uint2 b0v = *(const uint2*)(BMw + rl0 * BM_STRIDE + kt * 2);
            uint2 b1v = *(const uint2*)(BMw + (rl0 + 8) * BM_STRIDE + kt * 2);
            bits0 = ((uint64_t)b0v.y << 32 | b0v.x) >> j0;
            bits1 = ((uint64_t)b1v.y << 32 | b1v.x) >> j0;
        }
        uint32_t pp[8][4];
#pragma unroll
        for (int nb = 0; nb < 8; ++nb) {
            const uint32_t s0 = (uint32_t)(bits0 >> (nb * 8));
            const uint32_t s1 = (uint32_t)(bits1 >> (nb * 8));
            float p0 = (s0 & 1) ? __expf(sacc[nb][0] * 0.125f) : 0.f;
            float p1 = (s0 & 2) ? __expf(sacc[nb][1] * 0.125f) : 0.f;
            float p2 = (s1 & 1) ? __expf(sacc[nb][2] * 0.125f) : 0.f;
            float p3 = (s1 & 2) ? __expf(sacc[nb][3] * 0.125f) : 0.f;
            rs0 += p0 + p1;
            rs1 += p2 + p3;
            pp[nb][0] = f2tf(p0);   // a0 <- c0
            pp[nb][1] = f2tf(p2);   // a1 <- c2
            pp[nb][2] = f2tf(p1);   // a2 <- c1
            pp[nb][3] = f2tf(p3);   // a3 <- c3
        }

        // ---- O += P V  (V k-rows pre-permuted so A = pp directly) ----
        const uint32_t aV = bufb + laneV;
#pragma unroll
        for (int s = 0; s < 8; ++s) {
#pragma unroll
            for (int nb = 0; nb < 8; ++nb) {
                const uint32_t ad = aV + s * (8 * PITCHB) + nb * 32;
                const uint32_t b0 = lds32(ad);
                const uint32_t b1 = lds32(ad + 4 * PITCHB);
                mma_tf32(oacc[nb], pp[s], b0, b1);
            }
        }

        __syncthreads();
        issue_kv(kt + 2, b);
    }

    // ---- row sums: reduce 4 lanes per row, invert ----
    rs0 += __shfl_xor_sync(0xffffffffu, rs0, 1);
    rs0 += __shfl_xor_sync(0xffffffffu, rs0, 2);
    rs1 += __shfl_xor_sync(0xffffffffu, rs1, 1);
    rs1 += __shfl_xor_sync(0xffffffffu, rs1, 2);
    if ((l & 3) == 0) {
        rowsum[rl0]     = rs0;
        rowsum[rl0 + 8] = rs1;
    }
    __syncthreads();
    if (tid < TQ) rowsum[tid] = 1.0f / rowsum[tid];
    __syncthreads();

    const float inv0 = rowsum[rl0];
    const float inv1 = rowsum[rl0 + 8];

    // ---- write normalized O ----
    {
        float* or0 = Og + (size_t)r0 * DHEAD + (l & 3) * 2;
        float* or8 = or0 + 8 * DHEAD;
#pragma unroll
        for (int nb = 0; nb < 8; ++nb) {
            *(float2*)(or0 + nb * 8) = make_float2(oacc[nb][0] * inv0, oacc[nb][1] * inv0);
            *(float2*)(or8 + nb * 8) = make_float2(oacc[nb][2] * inv1, oacc[nb][3] * inv1);
        }
    }
    __syncthreads();

    // ============================ PASS 2: normalized attention ============================
    issue_k(0, 0);
    issue_k(1, 1);

    float* ab0 = Ag + (size_t)r0 * SLEN + (l & 3) * 2;

    for (int kt = 0; kt < NKT; ++kt) {
        const int b = kt & 1;
        const uint32_t bufb = smb + b * BUF_B;

        asm volatile("cp.async.wait_group 1;" ::: "memory");
        __syncthreads();
        // K only: 18432 B = 1152 f4 -> 4.5/thread
        {
            const uint32_t a0 = smb + b * BUF_B + tid * 16;
            for (int j = 0; j < 5; ++j) {
                const int idx = tid + j * NTHREADS;
                if (idx < 1152) {
                    const uint32_t ad = a0 + j * (NTHREADS * 16);
                    uint32_t x, y, z, t;
                    asm volatile("ld.shared.v4.b32 {%0,%1,%2,%3}, [%4];"
                                 : "=r"(x), "=r"(y), "=r"(z), "=r"(t) : "r"(ad));
                    x = f2tf(__uint_as_float(x)); y = f2tf(__uint_as_float(y));
                    z = f2tf(__uint_as_float(z)); t = f2tf(__uint_as_float(t));
                    asm volatile("st.shared.v4.b32 [%0], {%1,%2,%3,%4};"
                                 :: "r"(ad), "r"(x), "r"(y), "r"(z), "r"(t));
                }
            }
        }
        __syncthreads();

        // ---- S recompute ----
        float sacc[8][4];
#pragma unroll
        for (int nb = 0; nb < 8; ++nb) { sacc[nb][0]=0.f; sacc[nb][1]=0.f; sacc[nb][2]=0.f; sacc[nb][3]=0.f; }
        const uint32_t aK = bufb + laneK;
#pragma unroll
        for (int s = 0; s < 8; ++s) {
#pragma unroll
            for (int nb = 0; nb < 8; ++nb) {
                const uint32_t ad = aK + nb * (8 * PITCHB) + s * 32;
                const uint32_t b0 = lds32(ad);
                const uint32_t b1 = lds32(ad + 16);
                mma_tf32(sacc[nb], qa[s], b0, b1);
            }
        }

        // ---- exp * inv, write normalized attention once ----
        uint64_t bits0, bits1;
        {
            uint2 b0v = *(const uint2*)(BMw + rl0 * BM_STRIDE + kt * 2);
            uint2 b1v = *(const uint2*)(BMw + (rl0 + 8) * BM_STRIDE + kt * 2);
            bits0 = ((uint64_t)b0v.y << 32 | b0v.x) >> j0;
            bits1 = ((uint64_t)b1v.y << 32 | b1v.x) >> j0;
        }
        float* ar0 = ab0 + kt * TK;
        float* ar8 = ar0 + 8 * SLEN;
#pragma unroll
        for (int nb = 0; nb < 8; ++nb) {
            const uint32_t s0 = (uint32_t)(bits0 >> (nb * 8));
            const uint32_t s1 = (uint32_t)(bits1 >> (nb * 8));
            float p0 = (s0 & 1) ? __expf(sacc[nb][0] * 0.125f) * inv0 : 0.f;
            float p1 = (s0 & 2) ? __expf(sacc[nb][1] * 0.125f) * inv0 : 0.f;
            float p2 = (s1 & 1) ? __expf(sacc[nb][2] * 0.125f) * inv1 : 0.f;
            float p3 = (s1 & 2) ? __expf(sacc[nb][3] * 0.125f) * inv1 : 0.f;
            *(float2*)(ar0 + nb * 8) = make_float2(p0, p1);
            *(float2*)(ar8 + nb * 8) = make_float2(p2, p3);
        }

        __syncthreads();
        issue_k(kt + 2, b);
    }
}

extern "C" void kernel_launch(void* const* d_in, const int* in_sizes, int n_in,
                              void* d_out, int out_size)
{
    const float* Q    = (const float*)d_in[0];
    const float* K    = (const float*)d_in[1];
    const float* V    = (const float*)d_in[2];
    const int*   mask = (const int*)d_in[3];
    (void)in_sizes; (void)n_in; (void)out_size;

    float* out  = (float*)d_out;
    float* attn = out + OUT_ELEMS;

    static int configured = 0;
    if (!configured) {
        cudaFuncSetAttribute(sdpa_tf32_kernel,
                             cudaFuncAttributeMaxDynamicSharedMemorySize, SMEM_BYTES);
        configured = 1;
    }

    dim3 grid(SLEN / TQ, BHN);   // (16, 64)
    sdpa_tf32_kernel<<<grid, NTHREADS, SMEM_BYTES>>>(Q, K, V, mask, out, attn);
}

// round 10
// speedup vs baseline: 1.5232x; 1.1116x over previous
#include <cuda_runtime.h>
#include <cstdint>

#define SLEN    2048
#define DHEAD   64
#define BHN     64
#define TQ      128
#define TK      64
#define NTHREADS 256
#define NKT     (SLEN / TK)
#define OUT_ELEMS ((size_t)BHN * SLEN * DHEAD)   // 8,388,608

#define PITCHK  288                     // K & VT pitch bytes (72 words)
#define PITCHS  272                     // V stage pitch bytes (68 words)
#define KBUF    (64 * PITCHK)           // 18432
#define VSBUF   (64 * PITCHS)           // 17408

// ---- dynamic smem layout (bytes) ----
#define OFF_K0  0
#define OFF_K1  18432
#define OFF_VS  36864
#define OFF_VT  54272
#define OFF_BM  72704                   // 128 rows x 68 words = 34816
#define OFF_RS  107520
#define SMEM_BYTES (OFF_RS + 512)       // 108032 -> 2 CTAs/SM
#define BM_STRIDE 68

static __device__ __forceinline__ uint32_t smem_u32(const void* p) {
    uint32_t a;
    asm("{ .reg .u64 t; cvta.to.shared.u64 t, %1; cvt.u32.u64 %0, t; }" : "=r"(a) : "l"(p));
    return a;
}
static __device__ __forceinline__ void cp16(uint32_t sm, const void* g) {
    asm volatile("cp.async.cg.shared.global [%0], [%1], 16;" :: "r"(sm), "l"(g));
}
static __device__ __forceinline__ uint32_t f2tf(float f) {
    uint32_t u;
    asm("cvt.rna.tf32.f32 %0, %1;" : "=r"(u) : "f"(f));
    return u;
}
static __device__ __forceinline__ void mma_tf32(float* c, const uint32_t* a,
                                                uint32_t b0, uint32_t b1) {
    asm volatile("mma.sync.aligned.m16n8k8.row.col.f32.tf32.tf32.f32 "
                 "{%0,%1,%2,%3}, {%4,%5,%6,%7}, {%8,%9}, {%0,%1,%2,%3};"
                 : "+f"(c[0]), "+f"(c[1]), "+f"(c[2]), "+f"(c[3])
                 : "r"(a[0]), "r"(a[1]), "r"(a[2]), "r"(a[3]), "r"(b0), "r"(b1));
}
static __device__ __forceinline__ void lds64(uint32_t& a, uint32_t& b, uint32_t addr) {
    asm volatile("ld.shared.v2.b32 {%0,%1}, [%2];" : "=r"(a), "=r"(b) : "r"(addr));
}

__global__ void __launch_bounds__(NTHREADS, 2)
sdpa_tf32_kernel(const float* __restrict__ Qg_all,
                 const float* __restrict__ Kg_all,
                 const float* __restrict__ Vg_all,
                 const int*   __restrict__ Mg_all,
                 float* __restrict__ Og_all,
                 float* __restrict__ Ag_all)
{
    extern __shared__ uint8_t smem[];
    const uint32_t smb = smem_u32(smem);
    uint32_t* BMw = (uint32_t*)(smem + OFF_BM);
    float* rowsum = (float*)(smem + OFF_RS);

    const int tid = threadIdx.x;
    const int w   = tid >> 5;
    const int l   = tid & 31;
    const int bh  = blockIdx.y;
    const int q0  = blockIdx.x * TQ;

    const float* Qg = Qg_all + (size_t)bh * SLEN * DHEAD;
    const float* Kg = Kg_all + (size_t)bh * SLEN * DHEAD;
    const float* Vg = Vg_all + (size_t)bh * SLEN * DHEAD;
    const int*   Mg = Mg_all + (size_t)bh * SLEN * SLEN;
    float*       Og = Og_all + (size_t)bh * SLEN * DHEAD;
    float*       Ag = Ag_all + (size_t)bh * SLEN * SLEN;

    auto issue_k = [&](int kt, int b) {
        if (kt < NKT) {
            const float* Kt = Kg + (size_t)kt * TK * DHEAD;
            const uint32_t base = smb + OFF_K0 + b * KBUF;
#pragma unroll
            for (int j = 0; j < 4; ++j) {
                const int idx = tid + j * NTHREADS;
                const int row = idx >> 4, ch = idx & 15;
                cp16(base + row * PITCHK + ch * 16, Kt + row * DHEAD + ch * 4);
            }
        }
        asm volatile("cp.async.commit_group;" ::: "memory");
    };
    auto issue_v = [&](int kt) {
        if (kt < NKT) {
            const float* Vt = Vg + (size_t)kt * TK * DHEAD;
            const uint32_t base = smb + OFF_VS;
#pragma unroll
            for (int j = 0; j < 4; ++j) {
                const int idx = tid + j * NTHREADS;
                const int row = idx >> 4, ch = idx & 15;
                cp16(base + row * PITCHS + ch * 16, Vt + row * DHEAD + ch * 4);
            }
        }
        asm volatile("cp.async.commit_group;" ::: "memory");
    };
    // K stage: in-place RNA tf32 (1152 float4)
    auto sweep_k = [&](int b) {
        const uint32_t a0 = smb + OFF_K0 + b * KBUF;
        for (int j = 0; j < 5; ++j) {
            const int idx = tid + j * NTHREADS;
            if (idx < 1152) {
                const uint32_t ad = a0 + idx * 16;
                uint32_t x, y, z, t;
                asm volatile("ld.shared.v4.b32 {%0,%1,%2,%3}, [%4];"
                             : "=r"(x), "=r"(y), "=r"(z), "=r"(t) : "r"(ad));
                x = f2tf(__uint_as_float(x)); y = f2tf(__uint_as_float(y));
                z = f2tf(__uint_as_float(z)); t = f2tf(__uint_as_float(t));
                asm volatile("st.shared.v4.b32 [%0], {%1,%2,%3,%4};"
                             :: "r"(ad), "r"(x), "r"(y), "r"(z), "r"(t));
            }
        }
    };
    // VS [k][d] -> VT [d][k] with f2tf (1024 chunks)
    auto transpose_v = [&]() {
#pragma unroll
        for (int j = 0; j < 4; ++j) {
            const int idx = tid + j * NTHREADS;
            const int k = idx & 63, dc = idx >> 6;       // dc 0..15
            const uint32_t sa = smb + OFF_VS + k * PITCHS + dc * 16;
            uint32_t x, y, z, t;
            asm volatile("ld.shared.v4.b32 {%0,%1,%2,%3}, [%4];"
                         : "=r"(x), "=r"(y), "=r"(z), "=r"(t) : "r"(sa));
            x = f2tf(__uint_as_float(x)); y = f2tf(__uint_as_float(y));
            z = f2tf(__uint_as_float(z)); t = f2tf(__uint_as_float(t));
            const uint32_t da = smb + OFF_VT + (dc * 4) * PITCHK + k * 4;
            asm volatile("st.shared.b32 [%0], %1;" :: "r"(da),              "r"(x));
            asm volatile("st.shared.b32 [%0], %1;" :: "r"(da + PITCHK),     "r"(y));
            asm volatile("st.shared.b32 [%0], %1;" :: "r"(da + 2 * PITCHK), "r"(z));
            asm volatile("st.shared.b32 [%0], %1;" :: "r"(da + 3 * PITCHK), "r"(t));
        }
    };

    // prologue: V(0), K(0), K(1)
    issue_v(0);
    issue_k(0, 0);
    issue_k(1, 1);

    // ================= bit-packed mask: 128 rows x 2048 bits =================
    for (int base = 0; base < 8192; base += 64) {
        const int w0idx = base + w * 8;
        int vals[8];
#pragma unroll
        for (int j = 0; j < 8; ++j) {
            const int widx = w0idx + j;
            vals[j] = Mg[(size_t)(q0 + (widx >> 6)) * SLEN + (widx & 63) * 32 + l];
        }
#pragma unroll
        for (int j = 0; j < 8; ++j) {
            const unsigned bal = __ballot_sync(0xffffffffu, vals[j] != 0);
            const int widx = w0idx + j;
            if (l == 0) BMw[(widx >> 6) * BM_STRIDE + (widx & 63)] = bal;
        }
    }

    // ---- Q A-fragments (tf32, relabeled kpos: p -> d = 2p / 2(p-4)+1) ----
    const int rl0 = w * 16 + (l >> 2);
    const int r0  = q0 + rl0;
    uint32_t qa[8][4];
    {
        const float* Qr0 = Qg + (size_t)r0 * DHEAD;
#pragma unroll
        for (int s = 0; s < 8; ++s) {
            const int d0 = s * 8 + (l & 3) * 2;
            qa[s][0] = f2tf(Qr0[d0]);
            qa[s][1] = f2tf(Qr0[8 * DHEAD + d0]);
            qa[s][2] = f2tf(Qr0[d0 + 1]);
            qa[s][3] = f2tf(Qr0[8 * DHEAD + d0 + 1]);
        }
    }

    // per-lane base offset (same formula for K and VT tiles)
    const uint32_t laneB = (uint32_t)((l >> 2) * PITCHK + (l & 3) * 8);
    const int j0 = (l & 3) * 2;

    float oacc[8][4];
#pragma unroll
    for (int nb = 0; nb < 8; ++nb) { oacc[nb][0]=0.f; oacc[nb][1]=0.f; oacc[nb][2]=0.f; oacc[nb][3]=0.f; }
    float rs0 = 0.f, rs1 = 0.f;

    // ============================ PASS 1: rowsums + O ============================
    for (int kt = 0; kt < NKT; ++kt) {
        const int b = kt & 1;

        asm volatile("cp.async.wait_group 1;" ::: "memory");   // K(kt), V(kt) ready
        __syncthreads();

        transpose_v();        // VS -> VT (tf32)
        sweep_k(b);           // K stage -> tf32 in place
        __syncthreads();

        issue_v(kt + 1);      // VS free now

        // ---- S = Q K^T (LDS.64 B-frags, conflict-free) ----
        float sacc[8][4];
#pragma unroll
        for (int nb = 0; nb < 8; ++nb) { sacc[nb][0]=0.f; sacc[nb][1]=0.f; sacc[nb][2]=0.f; sacc[nb][3]=0.f; }
        const uint32_t aK = smb + OFF_K0 + b * KBUF + laneB;
#pragma unroll
        for (int s = 0; s < 8; ++s) {
#pragma unroll
            for (int nb = 0; nb < 8; ++nb) {
                uint32_t b0, b1;
                lds64(b0, b1, aK + nb * (8 * PITCHK) + s * 32);
                mma_tf32(sacc[nb], qa[s], b0, b1);
            }
        }

        // ---- mask bits, exp, rowsum, P->A frags ({c0,c2,c1,c3}) ----
        uint64_t bits0, bits1;
        {
            uint2 b0v = *(const uint2*)(BMw + rl0 * BM_STRIDE + kt * 2);
            uint2 b1v = *(const uint2*)(BMw + (rl0 + 8) * BM_STRIDE + kt * 2);
            bits0 = ((uint64_t)b0v.y << 32 | b0v.x) >> j0;
            bits1 = ((uint64_t)b1v.y << 32 | b1v.x) >> j0;
        }
        uint32_t pp[8][4];
#pragma unroll
        for (int nb = 0; nb < 8; ++nb) {
            const uint32_t s0 = (uint32_t)(bits0 >> (nb * 8));
            const uint32_t s1 = (uint32_t)(bits1 >> (nb * 8));
            float p0 = (s0 & 1) ? __expf(sacc[nb][0] * 0.125f) : 0.f;
            float p1 = (s0 & 2) ? __expf(sacc[nb][1] * 0.125f) : 0.f;
            float p2 = (s1 & 1) ? __expf(sacc[nb][2] * 0.125f) : 0.f;
            float p3 = (s1 & 2) ? __expf(sacc[nb][3] * 0.125f) : 0.f;
            rs0 += p0 + p1;
            rs1 += p2 + p3;
            pp[nb][0] = f2tf(p0);
            pp[nb][1] = f2tf(p2);
            pp[nb][2] = f2tf(p1);
            pp[nb][3] = f2tf(p3);
        }

        // ---- O += P V  (VT natural layout, LDS.64 B-frags) ----
        const uint32_t aV = smb + OFF_VT + laneB;
#pragma unroll
        for (int s = 0; s < 8; ++s) {
#pragma unroll
            for (int nb = 0; nb < 8; ++nb) {
                uint32_t b0, b1;
                lds64(b0, b1, aV + nb * (8 * PITCHK) + s * 32);
                mma_tf32(oacc[nb], pp[s], b0, b1);
            }
        }

        __syncthreads();
        issue_k(kt + 2, b);
    }

    // ---- row sums: reduce 4 lanes per row, invert ----
    rs0 += __shfl_xor_sync(0xffffffffu, rs0, 1);
    rs0 += __shfl_xor_sync(0xffffffffu, rs0, 2);
    rs1 += __shfl_xor_sync(0xffffffffu, rs1, 1);
    rs1 += __shfl_xor_sync(0xffffffffu, rs1, 2);
    if ((l & 3) == 0) {
        rowsum[rl0]     = rs0;
        rowsum[rl0 + 8] = rs1;
    }
    __syncthreads();
    if (tid < TQ) rowsum[tid] = 1.0f / rowsum[tid];
    __syncthreads();

    const float inv0 = rowsum[rl0];
    const float inv1 = rowsum[rl0 + 8];

    // ---- write normalized O ----
    {
        float* or0 = Og + (size_t)r0 * DHEAD + (l & 3) * 2;
        float* or8 = or0 + 8 * DHEAD;
#pragma unroll
        for (int nb = 0; nb < 8; ++nb) {
            *(float2*)(or0 + nb * 8) = make_float2(oacc[nb][0] * inv0, oacc[nb][1] * inv0);
            *(float2*)(or8 + nb * 8) = make_float2(oacc[nb][2] * inv1, oacc[nb][3] * inv1);
        }
    }
    __syncthreads();

    // ============================ PASS 2: normalized attention ============================
    issue_k(0, 0);
    issue_k(1, 1);

    float* ab0 = Ag + (size_t)r0 * SLEN + (l & 3) * 2;

    for (int kt = 0; kt < NKT; ++kt) {
        const int b = kt & 1;

        asm volatile("cp.async.wait_group 1;" ::: "memory");
        __syncthreads();
        sweep_k(b);
        __syncthreads();

        // ---- S recompute (LDS.64) ----
        float sacc[8][4];
#pragma unroll
        for (int nb = 0; nb < 8; ++nb) { sacc[nb][0]=0.f; sacc[nb][1]=0.f; sacc[nb][2]=0.f; sacc[nb][3]=0.f; }
        const uint32_t aK = smb + OFF_K0 + b * KBUF + laneB;
#pragma unroll
        for (int s = 0; s < 8; ++s) {
#pragma unroll
            for (int nb = 0; nb < 8; ++nb) {
                uint32_t b0, b1;
                lds64(b0, b1, aK + nb * (8 * PITCHK) + s * 32);
                mma_tf32(sacc[nb], qa[s], b0, b1);
            }
        }

        // ---- exp * inv, write normalized attention once ----
        uint64_t bits0, bits1;
        {
            uint2 b0v = *(const uint2*)(BMw + rl0 * BM_STRIDE + kt * 2);
            uint2 b1v = *(const uint2*)(BMw + (rl0 + 8) * BM_STRIDE + kt * 2);
            bits0 = ((uint64_t)b0v.y << 32 | b0v.x) >> j0;
            bits1 = ((uint64_t)b1v.y << 32 | b1v.x) >> j0;
        }
        float* ar0 = ab0 + kt * TK;
        float* ar8 = ar0 + 8 * SLEN;
#pragma unroll
        for (int nb = 0; nb < 8; ++nb) {
            const uint32_t s0 = (uint32_t)(bits0 >> (nb * 8));
            const uint32_t s1 = (uint32_t)(bits1 >> (nb * 8));
            float p0 = (s0 & 1) ? __expf(sacc[nb][0] * 0.125f) * inv0 : 0.f;
            float p1 = (s0 & 2) ? __expf(sacc[nb][1] * 0.125f) * inv0 : 0.f;
            float p2 = (s1 & 1) ? __expf(sacc[nb][2] * 0.125f) * inv1 : 0.f;
            float p3 = (s1 & 2) ? __expf(sacc[nb][3] * 0.125f) * inv1 : 0.f;
            *(float2*)(ar0 + nb * 8) = make_float2(p0, p1);
            *(float2*)(ar8 + nb * 8) = make_float2(p2, p3);
        }

        __syncthreads();
        issue_k(kt + 2, b);
    }
}

extern "C" void kernel_launch(void* const* d_in, const int* in_sizes, int n_in,
                              void* d_out, int out_size)
{
    const float* Q    = (const float*)d_in[0];
    const float* K    = (const float*)d_in[1];
    const float* V    = (const float*)d_in[2];
    const int*   mask = (const int*)d_in[3];
    (void)in_sizes; (void)n_in; (void)out_size;

    float* out  = (float*)d_out;
    float* attn = out + OUT_ELEMS;

    static int configured = 0;
    if (!configured) {
        cudaFuncSetAttribute(sdpa_tf32_kernel,
                             cudaFuncAttributeMaxDynamicSharedMemorySize, SMEM_BYTES);
        configured = 1;
    }

    dim3 grid(SLEN / TQ, BHN);   // (16, 64)
    sdpa_tf32_kernel<<<grid, NTHREADS, SMEM_BYTES>>>(Q, K, V, mask, out, attn);
}